// round 12
// baseline (speedup 1.0000x reference)
#include <cuda_runtime.h>
#include <cuda_bf16.h>
#include <cstdint>

#define BB 4
#define NN 1024
#define INF 256
#define OUTF 256
#define NH 8
#define BN (BB*NN)

// ---------------- scratch (allocation-free) ----------------
__device__ float g_buf[BN*OUTF];            // g = h @ W  (4 MB)
__device__ float p1_buf[BN*OUTF];           // j-half-1 partial (4 MB)
__device__ float Lbuf[BN*16];               // [exp(el) x8, exp(.2el) x8]
__device__ float Rbuf[BN*16];               // [exp(er) x8, exp(.2er) x8]
__device__ float4 Rv_glob[BN*NH];           // (Rp*c, Rn*c, c, 0)
__device__ __align__(16) uint32_t Gpk_hi[BN*OUTF/2];  // packed bf16 pairs (2 MB)
__device__ __align__(16) uint32_t Gpk_lo[BN*OUTF/2];  // lo corrections   (2 MB)
__device__ uint32_t adj_bits[BB*32*1024];   // [b][jc][i] bitmask (512 KB)

typedef unsigned long long u64;

__device__ __forceinline__ void ffma2(u64& d, u64 a, u64 b) {
    asm("fma.rn.f32x2 %0, %1, %2, %0;" : "+l"(d) : "l"(a), "l"(b));
}
union U2 { u64 u; float2 f; };

__device__ __forceinline__ uint32_t bf2u(__nv_bfloat162 v) {
    return *reinterpret_cast<uint32_t*>(&v);
}
__device__ __forceinline__ void mma_bf16(float* d, const uint32_t* a,
                                         const uint32_t* b) {
    asm volatile(
        "mma.sync.aligned.m16n8k16.row.col.f32.bf16.bf16.f32 "
        "{%0,%1,%2,%3}, {%4,%5,%6,%7}, {%8,%9}, {%0,%1,%2,%3};"
        : "+f"(d[0]), "+f"(d[1]), "+f"(d[2]), "+f"(d[3])
        : "r"(a[0]), "r"(a[1]), "r"(a[2]), "r"(a[3]), "r"(b[0]), "r"(b[1]));
}

// ---------------------------------------------------------------------------
// K1: g = X @ W, 64x64 tile, 4x4 micro-tile, f32x2; epilogue computes el/er
// and writes the 4 exps directly (k_exp folded in).
// ---------------------------------------------------------------------------
__global__ __launch_bounds__(256) void k_gemm(const float* __restrict__ X,
                                              const float* __restrict__ W,
                                              const float* __restrict__ aw) {
    __shared__ __align__(16) float2 Xs2[16][64];
    __shared__ __align__(16) float  Ws [16][64];
    const int t = threadIdx.x;
    const int row0 = (blockIdx.x >> 2) * 64;
    const int cb   = (blockIdx.x & 3) * 64;
    const int tx = t & 15, ty = t >> 4;
    const int r0 = ty * 4, c0 = tx * 4;

    u64 acc[4][2];
#pragma unroll
    for (int r = 0; r < 4; r++) { acc[r][0] = 0ull; acc[r][1] = 0ull; }

    const int lr = t >> 2, lk4 = (t & 3) * 4;
    const int wk = t >> 4, wc = (t & 15) * 4;

    for (int k0 = 0; k0 < INF; k0 += 16) {
        float4 xv = *reinterpret_cast<const float4*>(&X[(row0 + lr) * INF + k0 + lk4]);
        float4 wv = *reinterpret_cast<const float4*>(&W[(k0 + wk) * OUTF + cb + wc]);
        __syncthreads();
        Xs2[lk4 + 0][lr] = make_float2(xv.x, xv.x);
        Xs2[lk4 + 1][lr] = make_float2(xv.y, xv.y);
        Xs2[lk4 + 2][lr] = make_float2(xv.z, xv.z);
        Xs2[lk4 + 3][lr] = make_float2(xv.w, xv.w);
        *reinterpret_cast<float4*>(&Ws[wk][wc]) = wv;
        __syncthreads();
#pragma unroll
        for (int kk = 0; kk < 16; kk++) {
            const ulonglong2* xp = reinterpret_cast<const ulonglong2*>(&Xs2[kk][r0]);
            ulonglong2 xa = xp[0], xb = xp[1];
            ulonglong2 wv2 = *reinterpret_cast<const ulonglong2*>(&Ws[kk][c0]);
            ffma2(acc[0][0], xa.x, wv2.x); ffma2(acc[0][1], xa.x, wv2.y);
            ffma2(acc[1][0], xa.y, wv2.x); ffma2(acc[1][1], xa.y, wv2.y);
            ffma2(acc[2][0], xb.x, wv2.x); ffma2(acc[2][1], xb.x, wv2.y);
            ffma2(acc[3][0], xb.y, wv2.x); ffma2(acc[3][1], xb.y, wv2.y);
        }
    }

    const float4* awp = reinterpret_cast<const float4*>(aw);
    float4 aL = awp[tx & 7];
    float4 aR = awp[8 + (tx & 7)];

#pragma unroll
    for (int r = 0; r < 4; r++) {
        U2 a, b; a.u = acc[r][0]; b.u = acc[r][1];
        float4 o = make_float4(a.f.x, a.f.y, b.f.x, b.f.y);
        *reinterpret_cast<float4*>(&g_buf[(row0 + r0 + r) * OUTF + cb + c0]) = o;

        float el = o.x*aL.x + o.y*aL.y + o.z*aL.z + o.w*aL.w;
        float er = o.x*aR.x + o.y*aR.y + o.z*aR.z + o.w*aR.w;
        el += __shfl_xor_sync(0xffffffffu, el, 1);
        el += __shfl_xor_sync(0xffffffffu, el, 2);
        el += __shfl_xor_sync(0xffffffffu, el, 4);
        er += __shfl_xor_sync(0xffffffffu, er, 1);
        er += __shfl_xor_sync(0xffffffffu, er, 2);
        er += __shfl_xor_sync(0xffffffffu, er, 4);
        if ((tx & 7) == 0) {
            int head = (cb >> 5) + (tx >> 3);
            int row = row0 + r0 + r;
            Lbuf[row * 16 + head]     = __expf(el);
            Lbuf[row * 16 + 8 + head] = __expf(0.2f * el);
            Rbuf[row * 16 + head]     = __expf(er);
            Rbuf[row * 16 + 8 + head] = __expf(0.2f * er);
        }
    }
}

// ---------------------------------------------------------------------------
// K_gpack: g -> packed bf16 hi/lo pair-words, transposed per (b,h,jc):
// word[((b*8+h)*32+jc)*512 + d*16 + p] = (bf16(g[j=2p]), bf16(g[j=2p+1])) @ dim d
// ---------------------------------------------------------------------------
__global__ __launch_bounds__(256) void k_gpack() {
    __shared__ float gs[32][264];
    const int t = threadIdx.x;
    const int b = blockIdx.x >> 5, jc = blockIdx.x & 31;

    const float4* src = reinterpret_cast<const float4*>(
        g_buf + (size_t)(b * NN + jc * 32) * OUTF);
#pragma unroll
    for (int m = 0; m < 8; m++) {
        int v = t + m * 256;
        int row = v >> 6, c4 = v & 63;
        float4 x = src[(size_t)row * 64 + c4];
        *reinterpret_cast<float4*>(&gs[row][c4 * 4]) = x;
    }
    __syncthreads();

    const int h = t >> 5, d = t & 31;
    uint32_t wh[16], wl[16];
#pragma unroll
    for (int p = 0; p < 16; p++) {
        float a  = gs[2 * p][h * 32 + d];
        float bf = gs[2 * p + 1][h * 32 + d];
        __nv_bfloat16 ha = __float2bfloat16(a);
        __nv_bfloat16 hb = __float2bfloat16(bf);
        __nv_bfloat16 la = __float2bfloat16(a - __bfloat162float(ha));
        __nv_bfloat16 lb = __float2bfloat16(bf - __bfloat162float(hb));
        wh[p] = (uint32_t)__bfloat16_as_ushort(ha) |
                ((uint32_t)__bfloat16_as_ushort(hb) << 16);
        wl[p] = (uint32_t)__bfloat16_as_ushort(la) |
                ((uint32_t)__bfloat16_as_ushort(lb) << 16);
    }
    size_t base = ((size_t)((b * 8 + h) * 32 + jc) << 9) + d * 16;
#pragma unroll
    for (int q = 0; q < 4; q++) {
        *reinterpret_cast<uint4*>(&Gpk_hi[base + 4 * q]) =
            make_uint4(wh[4*q], wh[4*q+1], wh[4*q+2], wh[4*q+3]);
        *reinterpret_cast<uint4*>(&Gpk_lo[base + 4 * q]) =
            make_uint4(wl[4*q], wl[4*q+1], wl[4*q+2], wl[4*q+3]);
    }
}

// ---------------------------------------------------------------------------
// K2: 1/s[b,j,h]; writes Rv_glob and bit-packs adj (ballot) transposed.
// ---------------------------------------------------------------------------
__global__ __launch_bounds__(512) void k_c(const float* __restrict__ adj) {
    __shared__ float ssum[16][32][8];
    const int t = threadIdx.x;
    const int b = blockIdx.x >> 5;
    const int j0 = (blockIdx.x & 31) * 32;
    const int jl = t & 31, ig = t >> 5;

    const float4* rrow = reinterpret_cast<const float4*>(&Rbuf[(b * NN + j0 + jl) * 16]);
    float4 rp0 = rrow[0], rp1 = rrow[1], rn0 = rrow[2], rn1 = rrow[3];
    float EPr[8] = {rp0.x, rp0.y, rp0.z, rp0.w, rp1.x, rp1.y, rp1.z, rp1.w};
    float ENr[8] = {rn0.x, rn0.y, rn0.z, rn0.w, rn1.x, rn1.y, rn1.z, rn1.w};

    float acc[8];
#pragma unroll
    for (int h = 0; h < 8; h++) acc[h] = 0.f;

    uint32_t* abits = adj_bits + ((size_t)(b * 32 + (j0 >> 5)) << 10);
    const float* adjcol = adj + (size_t)b * NN * NN + j0 + jl;
#pragma unroll 4
    for (int i = ig; i < NN; i += 16) {
        float a = __ldg(adjcol + (size_t)i * NN);
        uint32_t m = __ballot_sync(0xffffffffu, a != 0.0f);
        if (jl == 0) abits[i] = m;
        const float4* lr = reinterpret_cast<const float4*>(&Lbuf[(b * NN + i) * 16]);
        float4 lp0 = __ldg(&lr[0]), lp1 = __ldg(&lr[1]);
        float4 ln0 = __ldg(&lr[2]), ln1 = __ldg(&lr[3]);
        float EPl[8] = {lp0.x, lp0.y, lp0.z, lp0.w, lp1.x, lp1.y, lp1.z, lp1.w};
        float ENl[8] = {ln0.x, ln0.y, ln0.z, ln0.w, ln1.x, ln1.y, ln1.z, ln1.w};
#pragma unroll
        for (int h = 0; h < 8; h++) {
            float p = EPl[h] * EPr[h];
            float q = ENl[h] * ENr[h];
            float w = (p >= 1.0f) ? p : q;
            acc[h] = fmaf(a, w, acc[h]);
        }
    }
#pragma unroll
    for (int h = 0; h < 8; h++) ssum[ig][jl][h] = acc[h];
    __syncthreads();

    if (t < 256) {
        int jl2 = t >> 3, h = t & 7;
        float s = 0.f;
#pragma unroll
        for (int g = 0; g < 16; g++) s += ssum[g][jl2][h];
        float cc = 1.0f / s;
        int row = b * NN + j0 + jl2;
        float Rp = Rbuf[row * 16 + h] * cc;
        float Rn = Rbuf[row * 16 + 8 + h] * cc;
        Rv_glob[row * NH + h] = make_float4(Rp, Rn, cc, 0.f);
    }
}

// ---------------------------------------------------------------------------
// K3 (tensor, bf16 3-term): adj via bitmask (1 line / warp-chunk), G staged
// as pure copy from Gpk. Grid 512 = (jh, b, h, i-tile 128).
// ---------------------------------------------------------------------------
#define GSTR 20
struct SmemT {
    uint32_t Gh[2][32][GSTR];   // 5 KB
    uint32_t Gl[2][32][GSTR];   // 5 KB
    float4   Rv_s[2][32];       // 1 KB
};

__device__ __forceinline__ void stageG(SmemT& sm, int buf, int b, int jc,
                                       int h, int t) {
    const uint32_t* src = (t < 128 ? Gpk_hi : Gpk_lo) +
                          ((size_t)((b * 8 + h) * 32 + jc) << 9);
    int tt = t & 127;
    uint4 v = __ldg(reinterpret_cast<const uint4*>(src) + tt);
    int d = tt >> 2, w0 = (tt & 3) * 4;
    uint32_t* dstrow = (t < 128 ? sm.Gh[buf][d] : sm.Gl[buf][d]);
    *reinterpret_cast<uint4*>(&dstrow[w0]) = v;
}

__device__ __forceinline__ float selw(float Lp, float Ln, float4 rv) {
    float p = Lp * rv.x;
    float q = Ln * rv.y;
    return (p >= rv.z) ? p : q;
}

__global__ __launch_bounds__(256, 3) void k_aggmma(float* __restrict__ out) {
    __shared__ SmemT sm;
    const int t = threadIdx.x;
    const int bid = blockIdx.x;
    const int jh = bid >> 8;
    const int b  = (bid >> 6) & 3;
    const int h  = (bid >> 3) & 7;
    const int i0 = (bid & 7) * 128;
    float* dst = jh ? p1_buf : out;

    const int lane = t & 31;
    const int gq = lane >> 2, tid4 = lane & 3;
    const int m0 = (t >> 5) * 16;

    const int r0g = b * NN + i0 + m0 + gq;
    const float Lp0 = Lbuf[r0g * 16 + h],       Ln0 = Lbuf[r0g * 16 + 8 + h];
    const float Lp1 = Lbuf[(r0g + 8) * 16 + h], Ln1 = Lbuf[(r0g + 8) * 16 + 8 + h];

    float acc[4][4];
#pragma unroll
    for (int nt = 0; nt < 4; nt++)
#pragma unroll
        for (int c = 0; c < 4; c++) acc[nt][c] = 0.f;

    // prologue
    stageG(sm, 0, b, jh * 16, h, t);
    if (t < 32)
        sm.Rv_s[0][t] = __ldg(&Rv_glob[(b * NN + jh * 512 + t) * NH + h]);

#pragma unroll 1
    for (int n = 0; n < 16; n++) {
        const int jc = jh * 16 + n;
        const int buf = n & 1;

        // adj bitmasks: rows m0+gq, m0+gq+8 for cols jc*32..+31
        const uint32_t* abits = adj_bits + ((size_t)(b * 32 + jc) << 10) + i0;
        uint32_t bits0 = __ldg(abits + m0 + gq);
        uint32_t bits1 = __ldg(abits + m0 + gq + 8);

        __syncthreads();   // chunk n's G/Rv visible; prior reads of buf done

        if (n < 15) {
            stageG(sm, buf ^ 1, b, jc + 1, h, t);
            if (t < 32)
                sm.Rv_s[buf ^ 1][t] =
                    __ldg(&Rv_glob[(b * NN + (jc + 1) * 32 + t) * NH + h]);
        }

#pragma unroll
        for (int kg = 0; kg < 2; kg++) {
            float4 rv0 = sm.Rv_s[buf][kg * 16 + 4 * tid4 + 0];
            float4 rv1 = sm.Rv_s[buf][kg * 16 + 4 * tid4 + 1];
            float4 rv2 = sm.Rv_s[buf][kg * 16 + 4 * tid4 + 2];
            float4 rv3 = sm.Rv_s[buf][kg * 16 + 4 * tid4 + 3];
            const int bb = kg * 16 + 4 * tid4;
            float w0 = (bits0 & (1u << (bb + 0))) ? selw(Lp0, Ln0, rv0) : 0.f;
            float w1 = (bits0 & (1u << (bb + 1))) ? selw(Lp0, Ln0, rv1) : 0.f;
            float w2 = (bits0 & (1u << (bb + 2))) ? selw(Lp0, Ln0, rv2) : 0.f;
            float w3 = (bits0 & (1u << (bb + 3))) ? selw(Lp0, Ln0, rv3) : 0.f;
            float v0 = (bits1 & (1u << (bb + 0))) ? selw(Lp1, Ln1, rv0) : 0.f;
            float v1 = (bits1 & (1u << (bb + 1))) ? selw(Lp1, Ln1, rv1) : 0.f;
            float v2 = (bits1 & (1u << (bb + 2))) ? selw(Lp1, Ln1, rv2) : 0.f;
            float v3 = (bits1 & (1u << (bb + 3))) ? selw(Lp1, Ln1, rv3) : 0.f;

            __nv_bfloat162 hw01 = __floats2bfloat162_rn(w0, w1);
            __nv_bfloat162 hw23 = __floats2bfloat162_rn(w2, w3);
            __nv_bfloat162 hv01 = __floats2bfloat162_rn(v0, v1);
            __nv_bfloat162 hv23 = __floats2bfloat162_rn(v2, v3);
            __nv_bfloat162 lw01 = __floats2bfloat162_rn(
                w0 - __low2float(hw01), w1 - __high2float(hw01));
            __nv_bfloat162 lw23 = __floats2bfloat162_rn(
                w2 - __low2float(hw23), w3 - __high2float(hw23));
            __nv_bfloat162 lv01 = __floats2bfloat162_rn(
                v0 - __low2float(hv01), v1 - __high2float(hv01));
            __nv_bfloat162 lv23 = __floats2bfloat162_rn(
                v2 - __low2float(hv23), v3 - __high2float(hv23));

            uint32_t ah[4] = {bf2u(hw01), bf2u(hv01), bf2u(hw23), bf2u(hv23)};
            uint32_t al[4] = {bf2u(lw01), bf2u(lv01), bf2u(lw23), bf2u(lv23)};

#pragma unroll
            for (int nt = 0; nt < 4; nt++) {
                int row = nt * 8 + gq;
                int wofs = 8 * kg + 2 * tid4;
                uint2 bh2 = *reinterpret_cast<const uint2*>(&sm.Gh[buf][row][wofs]);
                uint2 bl2 = *reinterpret_cast<const uint2*>(&sm.Gl[buf][row][wofs]);
                uint32_t bh[2] = {bh2.x, bh2.y};
                uint32_t bl[2] = {bl2.x, bl2.y};
                mma_bf16(acc[nt], ah, bh);
                mma_bf16(acc[nt], ah, bl);
                mma_bf16(acc[nt], al, bh);
            }
        }
    }

    // epilogue: rows m0+gq, m0+gq+8; cols h*32 + nt*8 + 2*tid4
#pragma unroll
    for (int nt = 0; nt < 4; nt++) {
        float* op0 = dst + (size_t)r0g * OUTF + h * 32 + nt * 8 + 2 * tid4;
        float* op1 = op0 + 8 * OUTF;
        *reinterpret_cast<float2*>(op0) = make_float2(acc[nt][0], acc[nt][1]);
        *reinterpret_cast<float2*>(op1) = make_float2(acc[nt][2], acc[nt][3]);
    }
}

// ---------------------------------------------------------------------------
// K4: out += p1
// ---------------------------------------------------------------------------
__global__ __launch_bounds__(256) void k_comb(float* __restrict__ out) {
    int idx = blockIdx.x * 256 + threadIdx.x;
    float4* o4 = reinterpret_cast<float4*>(out);
    const float4* p4 = reinterpret_cast<const float4*>(p1_buf);
    float4 a = o4[idx], b = p4[idx];
    o4[idx] = make_float4(a.x + b.x, a.y + b.y, a.z + b.z, a.w + b.w);
}

// ---------------------------------------------------------------------------
extern "C" void kernel_launch(void* const* d_in, const int* in_sizes, int n_in,
                              void* d_out, int out_size) {
    const float* h_in = (const float*)d_in[0];
    const float* adj  = (const float*)d_in[1];
    const float* W    = (const float*)d_in[2];
    const float* aw   = (const float*)d_in[3];
    float* out = (float*)d_out;

    k_gemm<<<256, 256>>>(h_in, W, aw);
    k_gpack<<<128, 256>>>();
    k_c<<<(BB * NN) / 32, 512>>>(adj);
    k_aggmma<<<512, 256>>>(out);
    k_comb<<<BN * OUTF / 4 / 256, 256>>>(out);
}

// round 13
// speedup vs baseline: 1.6235x; 1.6235x over previous
#include <cuda_runtime.h>
#include <cuda_bf16.h>
#include <cstdint>

#define BB 4
#define NN 1024
#define INF 256
#define OUTF 256
#define NH 8
#define BN (BB*NN)

// ---------------- scratch (allocation-free) ----------------
__device__ float g_buf[BN*OUTF];    // g = h @ W  (4 MB)
__device__ float p1_buf[BN*OUTF];   // j-half-1 partial (4 MB)
__device__ float ELraw[BN*NH];
__device__ float ERraw[BN*NH];
__device__ float Lbuf[BN*16];       // [exp(el) x8, exp(.2el) x8]
__device__ float Rbuf[BN*16];       // [exp(er) x8, exp(.2er) x8]
__device__ float4 Rv_glob[BN*NH];   // (Rp*c, Rn*c, c, 0) per (b,j,h)
__device__ float psum[2*BN*NH];     // k_c partial sums (i-halves)

typedef unsigned long long u64;

__device__ __forceinline__ void ffma2(u64& d, u64 a, u64 b) {
    asm("fma.rn.f32x2 %0, %1, %2, %0;" : "+l"(d) : "l"(a), "l"(b));
}
union U2 { u64 u; float2 f; };

__device__ __forceinline__ uint32_t bf2u(__nv_bfloat162 v) {
    return *reinterpret_cast<uint32_t*>(&v);
}
__device__ __forceinline__ void mma_bf16(float* d, const uint32_t* a,
                                         const uint32_t* b) {
    asm volatile(
        "mma.sync.aligned.m16n8k16.row.col.f32.bf16.bf16.f32 "
        "{%0,%1,%2,%3}, {%4,%5,%6,%7}, {%8,%9}, {%0,%1,%2,%3};"
        : "+f"(d[0]), "+f"(d[1]), "+f"(d[2]), "+f"(d[3])
        : "r"(a[0]), "r"(a[1]), "r"(a[2]), "r"(a[3]), "r"(b[0]), "r"(b[1]));
}

// ---------------------------------------------------------------------------
// K1: g = X @ W, 64x64 tile, 4x4 micro-tile, f32x2, fused el/er epilogue
// (exps computed in-place).
// ---------------------------------------------------------------------------
__global__ __launch_bounds__(256) void k_gemm(const float* __restrict__ X,
                                              const float* __restrict__ W,
                                              const float* __restrict__ aw) {
    __shared__ __align__(16) float2 Xs2[16][64];
    __shared__ __align__(16) float  Ws [16][64];
    const int t = threadIdx.x;
    const int row0 = (blockIdx.x >> 2) * 64;
    const int cb   = (blockIdx.x & 3) * 64;
    const int tx = t & 15, ty = t >> 4;
    const int r0 = ty * 4, c0 = tx * 4;

    u64 acc[4][2];
#pragma unroll
    for (int r = 0; r < 4; r++) { acc[r][0] = 0ull; acc[r][1] = 0ull; }

    const int lr = t >> 2, lk4 = (t & 3) * 4;
    const int wk = t >> 4, wc = (t & 15) * 4;

    for (int k0 = 0; k0 < INF; k0 += 16) {
        float4 xv = *reinterpret_cast<const float4*>(&X[(row0 + lr) * INF + k0 + lk4]);
        float4 wv = *reinterpret_cast<const float4*>(&W[(k0 + wk) * OUTF + cb + wc]);
        __syncthreads();
        Xs2[lk4 + 0][lr] = make_float2(xv.x, xv.x);
        Xs2[lk4 + 1][lr] = make_float2(xv.y, xv.y);
        Xs2[lk4 + 2][lr] = make_float2(xv.z, xv.z);
        Xs2[lk4 + 3][lr] = make_float2(xv.w, xv.w);
        *reinterpret_cast<float4*>(&Ws[wk][wc]) = wv;
        __syncthreads();
#pragma unroll
        for (int kk = 0; kk < 16; kk++) {
            const ulonglong2* xp = reinterpret_cast<const ulonglong2*>(&Xs2[kk][r0]);
            ulonglong2 xa = xp[0], xb = xp[1];
            ulonglong2 wv2 = *reinterpret_cast<const ulonglong2*>(&Ws[kk][c0]);
            ffma2(acc[0][0], xa.x, wv2.x); ffma2(acc[0][1], xa.x, wv2.y);
            ffma2(acc[1][0], xa.y, wv2.x); ffma2(acc[1][1], xa.y, wv2.y);
            ffma2(acc[2][0], xb.x, wv2.x); ffma2(acc[2][1], xb.x, wv2.y);
            ffma2(acc[3][0], xb.y, wv2.x); ffma2(acc[3][1], xb.y, wv2.y);
        }
    }

    const float4* awp = reinterpret_cast<const float4*>(aw);
    float4 aL = awp[tx & 7];
    float4 aR = awp[8 + (tx & 7)];

#pragma unroll
    for (int r = 0; r < 4; r++) {
        U2 a, b; a.u = acc[r][0]; b.u = acc[r][1];
        float4 o = make_float4(a.f.x, a.f.y, b.f.x, b.f.y);
        *reinterpret_cast<float4*>(&g_buf[(row0 + r0 + r) * OUTF + cb + c0]) = o;

        float el = o.x*aL.x + o.y*aL.y + o.z*aL.z + o.w*aL.w;
        float er = o.x*aR.x + o.y*aR.y + o.z*aR.z + o.w*aR.w;
        el += __shfl_xor_sync(0xffffffffu, el, 1);
        el += __shfl_xor_sync(0xffffffffu, el, 2);
        el += __shfl_xor_sync(0xffffffffu, el, 4);
        er += __shfl_xor_sync(0xffffffffu, er, 1);
        er += __shfl_xor_sync(0xffffffffu, er, 2);
        er += __shfl_xor_sync(0xffffffffu, er, 4);
        if ((tx & 7) == 0) {
            int head = (cb >> 5) + (tx >> 3);
            int row = row0 + r0 + r;
            Lbuf[row * 16 + head]     = __expf(el);
            Lbuf[row * 16 + 8 + head] = __expf(0.2f * el);
            Rbuf[row * 16 + head]     = __expf(er);
            Rbuf[row * 16 + 8 + head] = __expf(0.2f * er);
        }
    }
}

// ---------------------------------------------------------------------------
// K2: partial column sums over one i-half. Grid 256 = (ihalf, b, j-chunk).
// psum[ih][(b*NN+j)*NH+h] = sum_{i in half} adj * wexp.
// ---------------------------------------------------------------------------
__global__ __launch_bounds__(512) void k_c(const float* __restrict__ adj) {
    __shared__ float ssum[16][32][8];
    const int t = threadIdx.x;
    const int ih = blockIdx.x >> 7;
    const int b = (blockIdx.x >> 5) & 3;
    const int j0 = (blockIdx.x & 31) * 32;
    const int jl = t & 31, ig = t >> 5;

    const float4* rrow = reinterpret_cast<const float4*>(&Rbuf[(b * NN + j0 + jl) * 16]);
    float4 rp0 = rrow[0], rp1 = rrow[1], rn0 = rrow[2], rn1 = rrow[3];
    float EPr[8] = {rp0.x, rp0.y, rp0.z, rp0.w, rp1.x, rp1.y, rp1.z, rp1.w};
    float ENr[8] = {rn0.x, rn0.y, rn0.z, rn0.w, rn1.x, rn1.y, rn1.z, rn1.w};

    float acc[8];
#pragma unroll
    for (int h = 0; h < 8; h++) acc[h] = 0.f;

    const int ibeg = ih * 512;
    const float* adjcol = adj + (size_t)b * NN * NN + j0 + jl;
#pragma unroll 4
    for (int i = ibeg + ig; i < ibeg + 512; i += 16) {
        float a = __ldg(adjcol + (size_t)i * NN);
        const float4* lr = reinterpret_cast<const float4*>(&Lbuf[(b * NN + i) * 16]);
        float4 lp0 = __ldg(&lr[0]), lp1 = __ldg(&lr[1]);
        float4 ln0 = __ldg(&lr[2]), ln1 = __ldg(&lr[3]);
        float EPl[8] = {lp0.x, lp0.y, lp0.z, lp0.w, lp1.x, lp1.y, lp1.z, lp1.w};
        float ENl[8] = {ln0.x, ln0.y, ln0.z, ln0.w, ln1.x, ln1.y, ln1.z, ln1.w};
#pragma unroll
        for (int h = 0; h < 8; h++) {
            float p = EPl[h] * EPr[h];
            float q = ENl[h] * ENr[h];
            float w = (p >= 1.0f) ? p : q;
            acc[h] = fmaf(a, w, acc[h]);
        }
    }
#pragma unroll
    for (int h = 0; h < 8; h++) ssum[ig][jl][h] = acc[h];
    __syncthreads();

    if (t < 256) {
        int jl2 = t >> 3, h = t & 7;
        float s = 0.f;
#pragma unroll
        for (int g = 0; g < 16; g++) s += ssum[g][jl2][h];
        psum[ih * BN * NH + (b * NN + j0 + jl2) * NH + h] = s;
    }
}

// ---------------------------------------------------------------------------
// K_rv: combine i-half partials -> Rv_glob = (Rp*c, Rn*c, c, 0).
// ---------------------------------------------------------------------------
__global__ __launch_bounds__(256) void k_rv() {
    int idx = blockIdx.x * 256 + threadIdx.x;     // < BN*NH
    float s = psum[idx] + psum[BN * NH + idx];
    float cc = 1.0f / s;
    int row = idx >> 3, h = idx & 7;
    float Rp = Rbuf[row * 16 + h] * cc;
    float Rn = Rbuf[row * 16 + 8 + h] * cc;
    Rv_glob[idx] = make_float4(Rp, Rn, cc, 0.f);
}

// ---------------------------------------------------------------------------
// K3 (tensor, bf16 m16n8k16 3-term) — identical to R11 (best known).
// k-permutation makes adj LDG.128-able; G packed bf16x2 hi/lo in smem,
// rows stride 20 words; double-buffered. Grid 512 = (jh, b, h, i-tile 128).
// ---------------------------------------------------------------------------
#define GSTR 20
struct SmemT {
    uint32_t Gh[2][32][GSTR];   // 5 KB
    uint32_t Gl[2][32][GSTR];   // 5 KB
    float4   Rv_s[2][32];       // 1 KB
};

__device__ __forceinline__ void stageG(SmemT& sm, int buf, int b, int j0,
                                       int h, int t) {
    const int jj = t >> 3;
    const int d0 = (t & 7) * 4;
    float4 gv = __ldg(reinterpret_cast<const float4*>(
        g_buf + (size_t)(b * NN + j0 + jj) * OUTF + h * 32 + d0));
    float vs[4] = {gv.x, gv.y, gv.z, gv.w};
    uint32_t myhi[4], mylo[4];
#pragma unroll
    for (int e = 0; e < 4; e++) {
        __nv_bfloat16 hb = __float2bfloat16(vs[e]);
        float hf = __bfloat162float(hb);
        __nv_bfloat16 lb = __float2bfloat16(vs[e] - hf);
        myhi[e] = (uint32_t)__bfloat16_as_ushort(hb);
        mylo[e] = (uint32_t)__bfloat16_as_ushort(lb);
    }
    const int p = jj >> 1;
    const bool evenj = (jj & 1) == 0;
#pragma unroll
    for (int e = 0; e < 4; e++) {
        uint32_t phi = __shfl_xor_sync(0xffffffffu, myhi[e], 8);
        uint32_t plo = __shfl_xor_sync(0xffffffffu, mylo[e], 8);
        if (evenj) sm.Gh[buf][d0 + e][p] = myhi[e] | (phi << 16);
        else       sm.Gl[buf][d0 + e][p] = plo | (mylo[e] << 16);
    }
}

__device__ __forceinline__ float selw(float Lp, float Ln, float4 rv) {
    float p = Lp * rv.x;
    float q = Ln * rv.y;
    return (p >= rv.z) ? p : q;
}

__global__ __launch_bounds__(256, 3) void k_aggmma(const float* __restrict__ adj,
                                                   float* __restrict__ out) {
    __shared__ SmemT sm;
    const int t = threadIdx.x;
    const int bid = blockIdx.x;
    const int jh = bid >> 8;
    const int b  = (bid >> 6) & 3;
    const int h  = (bid >> 3) & 7;
    const int i0 = (bid & 7) * 128;
    const int jbase = jh * 512;
    float* dst = jh ? p1_buf : out;

    const int lane = t & 31;
    const int gq = lane >> 2, tid4 = lane & 3;
    const int m0 = (t >> 5) * 16;

    const int r0g = b * NN + i0 + m0 + gq;
    const float Lp0 = Lbuf[r0g * 16 + h],       Ln0 = Lbuf[r0g * 16 + 8 + h];
    const float Lp1 = Lbuf[(r0g + 8) * 16 + h], Ln1 = Lbuf[(r0g + 8) * 16 + 8 + h];

    float acc[4][4];
#pragma unroll
    for (int nt = 0; nt < 4; nt++)
#pragma unroll
        for (int c = 0; c < 4; c++) acc[nt][c] = 0.f;

    // prologue
    stageG(sm, 0, b, jbase, h, t);
    if (t < 32)
        sm.Rv_s[0][t] = __ldg(&Rv_glob[(b * NN + jbase + t) * NH + h]);

    const float* arow0 = adj + (size_t)r0g * NN;
    const float* arow1 = arow0 + 8 * NN;

#pragma unroll 1
    for (int n = 0; n < 16; n++) {
        const int j0 = jbase + n * 32;
        const int buf = n & 1;

        // adj prefetch: 4 x LDG.128 (phys cols 4*tid4..+3, +16; rows gq, gq+8)
        float4 aA[2], aB[2];
        aA[0] = __ldg(reinterpret_cast<const float4*>(arow0 + j0 + 4 * tid4));
        aA[1] = __ldg(reinterpret_cast<const float4*>(arow0 + j0 + 16 + 4 * tid4));
        aB[0] = __ldg(reinterpret_cast<const float4*>(arow1 + j0 + 4 * tid4));
        aB[1] = __ldg(reinterpret_cast<const float4*>(arow1 + j0 + 16 + 4 * tid4));

        __syncthreads();   // chunk n's G/Rv visible; prior reads of buf done

        if (n < 15) {
            stageG(sm, buf ^ 1, b, j0 + 32, h, t);
            if (t < 32)
                sm.Rv_s[buf ^ 1][t] =
                    __ldg(&Rv_glob[(b * NN + j0 + 32 + t) * NH + h]);
        }

#pragma unroll
        for (int kg = 0; kg < 2; kg++) {
            float4 rv0 = sm.Rv_s[buf][kg * 16 + 4 * tid4 + 0];
            float4 rv1 = sm.Rv_s[buf][kg * 16 + 4 * tid4 + 1];
            float4 rv2 = sm.Rv_s[buf][kg * 16 + 4 * tid4 + 2];
            float4 rv3 = sm.Rv_s[buf][kg * 16 + 4 * tid4 + 3];
            const float* avA = &aA[kg].x;
            const float* avB = &aB[kg].x;
            float w0 = avA[0] * selw(Lp0, Ln0, rv0);
            float w1 = avA[1] * selw(Lp0, Ln0, rv1);
            float w2 = avA[2] * selw(Lp0, Ln0, rv2);
            float w3 = avA[3] * selw(Lp0, Ln0, rv3);
            float v0 = avB[0] * selw(Lp1, Ln1, rv0);
            float v1 = avB[1] * selw(Lp1, Ln1, rv1);
            float v2 = avB[2] * selw(Lp1, Ln1, rv2);
            float v3 = avB[3] * selw(Lp1, Ln1, rv3);

            __nv_bfloat162 hw01 = __floats2bfloat162_rn(w0, w1);
            __nv_bfloat162 hw23 = __floats2bfloat162_rn(w2, w3);
            __nv_bfloat162 hv01 = __floats2bfloat162_rn(v0, v1);
            __nv_bfloat162 hv23 = __floats2bfloat162_rn(v2, v3);
            __nv_bfloat162 lw01 = __floats2bfloat162_rn(
                w0 - __low2float(hw01), w1 - __high2float(hw01));
            __nv_bfloat162 lw23 = __floats2bfloat162_rn(
                w2 - __low2float(hw23), w3 - __high2float(hw23));
            __nv_bfloat162 lv01 = __floats2bfloat162_rn(
                v0 - __low2float(hv01), v1 - __high2float(hv01));
            __nv_bfloat162 lv23 = __floats2bfloat162_rn(
                v2 - __low2float(hv23), v3 - __high2float(hv23));

            uint32_t ah[4] = {bf2u(hw01), bf2u(hv01), bf2u(hw23), bf2u(hv23)};
            uint32_t al[4] = {bf2u(lw01), bf2u(lv01), bf2u(lw23), bf2u(lv23)};

#pragma unroll
            for (int nt = 0; nt < 4; nt++) {
                int row = nt * 8 + gq;
                int wofs = 8 * kg + 2 * tid4;
                uint2 bh2 = *reinterpret_cast<const uint2*>(&sm.Gh[buf][row][wofs]);
                uint2 bl2 = *reinterpret_cast<const uint2*>(&sm.Gl[buf][row][wofs]);
                uint32_t bh[2] = {bh2.x, bh2.y};
                uint32_t bl[2] = {bl2.x, bl2.y};
                mma_bf16(acc[nt], ah, bh);
                mma_bf16(acc[nt], ah, bl);
                mma_bf16(acc[nt], al, bh);
            }
        }
    }

    // epilogue: rows m0+gq, m0+gq+8; cols h*32 + nt*8 + 2*tid4
#pragma unroll
    for (int nt = 0; nt < 4; nt++) {
        float* op0 = dst + (size_t)r0g * OUTF + h * 32 + nt * 8 + 2 * tid4;
        float* op1 = op0 + 8 * OUTF;
        *reinterpret_cast<float2*>(op0) = make_float2(acc[nt][0], acc[nt][1]);
        *reinterpret_cast<float2*>(op1) = make_float2(acc[nt][2], acc[nt][3]);
    }
}

// ---------------------------------------------------------------------------
// K4: out += p1   (combine j-halves)
// ---------------------------------------------------------------------------
__global__ __launch_bounds__(256) void k_comb(float* __restrict__ out) {
    int idx = blockIdx.x * 256 + threadIdx.x;    // < BN*OUTF/4
    float4* o4 = reinterpret_cast<float4*>(out);
    const float4* p4 = reinterpret_cast<const float4*>(p1_buf);
    float4 a = o4[idx], b = p4[idx];
    o4[idx] = make_float4(a.x + b.x, a.y + b.y, a.z + b.z, a.w + b.w);
}

// ---------------------------------------------------------------------------
extern "C" void kernel_launch(void* const* d_in, const int* in_sizes, int n_in,
                              void* d_out, int out_size) {
    const float* h_in = (const float*)d_in[0];
    const float* adj  = (const float*)d_in[1];
    const float* W    = (const float*)d_in[2];
    const float* aw   = (const float*)d_in[3];
    float* out = (float*)d_out;

    k_gemm<<<256, 256>>>(h_in, W, aw);
    k_c<<<2 * (BB * NN) / 32, 512>>>(adj);
    k_rv<<<BN * NH / 256, 256>>>();
    k_aggmma<<<512, 256>>>(adj, out);
    k_comb<<<BN * OUTF / 4 / 256, 256>>>(out);
}

// round 14
// speedup vs baseline: 1.6457x; 1.0137x over previous
#include <cuda_runtime.h>
#include <cuda_bf16.h>
#include <cstdint>

#define BB 4
#define NN 1024
#define INF 256
#define OUTF 256
#define NH 8
#define BN (BB*NN)

// ---------------- scratch (allocation-free) ----------------
__device__ float g_buf[BN*OUTF];    // g = h @ W  (4 MB)
__device__ float p1_buf[BN*OUTF];   // j-half-1 partial (4 MB)
__device__ float Lbuf[BN*16];       // [exp(el) x8, exp(.2el) x8]
__device__ float Rbuf[BN*16];       // [exp(er) x8, exp(.2er) x8]
__device__ float4 Rv_glob[BN*NH];   // (Rp*c, Rn*c, c, 0) per (b,j,h)
__device__ float psum[4*BN*NH];     // k_c partial sums (i-quarters)

typedef unsigned long long u64;

__device__ __forceinline__ void ffma2(u64& d, u64 a, u64 b) {
    asm("fma.rn.f32x2 %0, %1, %2, %0;" : "+l"(d) : "l"(a), "l"(b));
}
union U2 { u64 u; float2 f; };

__device__ __forceinline__ uint32_t bf2u(__nv_bfloat162 v) {
    return *reinterpret_cast<uint32_t*>(&v);
}
__device__ __forceinline__ void mma_bf16(float* d, const uint32_t* a,
                                         const uint32_t* b) {
    asm volatile(
        "mma.sync.aligned.m16n8k16.row.col.f32.bf16.bf16.f32 "
        "{%0,%1,%2,%3}, {%4,%5,%6,%7}, {%8,%9}, {%0,%1,%2,%3};"
        : "+f"(d[0]), "+f"(d[1]), "+f"(d[2]), "+f"(d[3])
        : "r"(a[0]), "r"(a[1]), "r"(a[2]), "r"(a[3]), "r"(b[0]), "r"(b[1]));
}

// ---------------------------------------------------------------------------
// K1: g = X @ W, 64x64 tile, 4x4 micro-tile, f32x2, fused el/er+exp epilogue.
// Software-pipelined: k+1 tile's LDGs issue before k's compute.
// ---------------------------------------------------------------------------
__global__ __launch_bounds__(256) void k_gemm(const float* __restrict__ X,
                                              const float* __restrict__ W,
                                              const float* __restrict__ aw) {
    __shared__ __align__(16) float2 Xs2[16][64];
    __shared__ __align__(16) float  Ws [16][64];
    const int t = threadIdx.x;
    const int row0 = (blockIdx.x >> 2) * 64;
    const int cb   = (blockIdx.x & 3) * 64;
    const int tx = t & 15, ty = t >> 4;
    const int r0 = ty * 4, c0 = tx * 4;

    u64 acc[4][2];
#pragma unroll
    for (int r = 0; r < 4; r++) { acc[r][0] = 0ull; acc[r][1] = 0ull; }

    const int lr = t >> 2, lk4 = (t & 3) * 4;
    const int wk = t >> 4, wc = (t & 15) * 4;

    // prologue loads
    float4 xv = *reinterpret_cast<const float4*>(&X[(row0 + lr) * INF + lk4]);
    float4 wv = *reinterpret_cast<const float4*>(&W[wk * OUTF + cb + wc]);

    for (int k0 = 0; k0 < INF; k0 += 16) {
        __syncthreads();
        Xs2[lk4 + 0][lr] = make_float2(xv.x, xv.x);
        Xs2[lk4 + 1][lr] = make_float2(xv.y, xv.y);
        Xs2[lk4 + 2][lr] = make_float2(xv.z, xv.z);
        Xs2[lk4 + 3][lr] = make_float2(xv.w, xv.w);
        *reinterpret_cast<float4*>(&Ws[wk][wc]) = wv;
        __syncthreads();
        if (k0 + 16 < INF) {   // prefetch next tile (overlaps compute below)
            xv = *reinterpret_cast<const float4*>(&X[(row0 + lr) * INF + k0 + 16 + lk4]);
            wv = *reinterpret_cast<const float4*>(&W[(k0 + 16 + wk) * OUTF + cb + wc]);
        }
#pragma unroll
        for (int kk = 0; kk < 16; kk++) {
            const ulonglong2* xp = reinterpret_cast<const ulonglong2*>(&Xs2[kk][r0]);
            ulonglong2 xa = xp[0], xb = xp[1];
            ulonglong2 wv2 = *reinterpret_cast<const ulonglong2*>(&Ws[kk][c0]);
            ffma2(acc[0][0], xa.x, wv2.x); ffma2(acc[0][1], xa.x, wv2.y);
            ffma2(acc[1][0], xa.y, wv2.x); ffma2(acc[1][1], xa.y, wv2.y);
            ffma2(acc[2][0], xb.x, wv2.x); ffma2(acc[2][1], xb.x, wv2.y);
            ffma2(acc[3][0], xb.y, wv2.x); ffma2(acc[3][1], xb.y, wv2.y);
        }
    }

    const float4* awp = reinterpret_cast<const float4*>(aw);
    float4 aL = awp[tx & 7];
    float4 aR = awp[8 + (tx & 7)];

#pragma unroll
    for (int r = 0; r < 4; r++) {
        U2 a, b; a.u = acc[r][0]; b.u = acc[r][1];
        float4 o = make_float4(a.f.x, a.f.y, b.f.x, b.f.y);
        *reinterpret_cast<float4*>(&g_buf[(row0 + r0 + r) * OUTF + cb + c0]) = o;

        float el = o.x*aL.x + o.y*aL.y + o.z*aL.z + o.w*aL.w;
        float er = o.x*aR.x + o.y*aR.y + o.z*aR.z + o.w*aR.w;
        el += __shfl_xor_sync(0xffffffffu, el, 1);
        el += __shfl_xor_sync(0xffffffffu, el, 2);
        el += __shfl_xor_sync(0xffffffffu, el, 4);
        er += __shfl_xor_sync(0xffffffffu, er, 1);
        er += __shfl_xor_sync(0xffffffffu, er, 2);
        er += __shfl_xor_sync(0xffffffffu, er, 4);
        if ((tx & 7) == 0) {
            int head = (cb >> 5) + (tx >> 3);
            int row = row0 + r0 + r;
            Lbuf[row * 16 + head]     = __expf(el);
            Lbuf[row * 16 + 8 + head] = __expf(0.2f * el);
            Rbuf[row * 16 + head]     = __expf(er);
            Rbuf[row * 16 + 8 + head] = __expf(0.2f * er);
        }
    }
}

// ---------------------------------------------------------------------------
// K2: partial column sums over one i-quarter. Grid 512 = (iq, b, j-chunk).
// psum[iq][(b*NN+j)*NH+h] = sum_{i in quarter} adj * wexp.
// ---------------------------------------------------------------------------
__global__ __launch_bounds__(512) void k_c(const float* __restrict__ adj) {
    __shared__ float ssum[16][32][8];
    const int t = threadIdx.x;
    const int iq = blockIdx.x >> 7;
    const int b = (blockIdx.x >> 5) & 3;
    const int j0 = (blockIdx.x & 31) * 32;
    const int jl = t & 31, ig = t >> 5;

    const float4* rrow = reinterpret_cast<const float4*>(&Rbuf[(b * NN + j0 + jl) * 16]);
    float4 rp0 = rrow[0], rp1 = rrow[1], rn0 = rrow[2], rn1 = rrow[3];
    float EPr[8] = {rp0.x, rp0.y, rp0.z, rp0.w, rp1.x, rp1.y, rp1.z, rp1.w};
    float ENr[8] = {rn0.x, rn0.y, rn0.z, rn0.w, rn1.x, rn1.y, rn1.z, rn1.w};

    float acc[8];
#pragma unroll
    for (int h = 0; h < 8; h++) acc[h] = 0.f;

    const int ibeg = iq * 256;
    const float* adjcol = adj + (size_t)b * NN * NN + j0 + jl;
#pragma unroll 4
    for (int i = ibeg + ig; i < ibeg + 256; i += 16) {
        float a = __ldg(adjcol + (size_t)i * NN);
        const float4* lr = reinterpret_cast<const float4*>(&Lbuf[(b * NN + i) * 16]);
        float4 lp0 = __ldg(&lr[0]), lp1 = __ldg(&lr[1]);
        float4 ln0 = __ldg(&lr[2]), ln1 = __ldg(&lr[3]);
        float EPl[8] = {lp0.x, lp0.y, lp0.z, lp0.w, lp1.x, lp1.y, lp1.z, lp1.w};
        float ENl[8] = {ln0.x, ln0.y, ln0.z, ln0.w, ln1.x, ln1.y, ln1.z, ln1.w};
#pragma unroll
        for (int h = 0; h < 8; h++) {
            float p = EPl[h] * EPr[h];
            float q = ENl[h] * ENr[h];
            float w = (p >= 1.0f) ? p : q;
            acc[h] = fmaf(a, w, acc[h]);
        }
    }
#pragma unroll
    for (int h = 0; h < 8; h++) ssum[ig][jl][h] = acc[h];
    __syncthreads();

    if (t < 256) {
        int jl2 = t >> 3, h = t & 7;
        float s = 0.f;
#pragma unroll
        for (int g = 0; g < 16; g++) s += ssum[g][jl2][h];
        psum[iq * BN * NH + (b * NN + j0 + jl2) * NH + h] = s;
    }
}

// ---------------------------------------------------------------------------
// K_rv: combine i-quarter partials -> Rv_glob = (Rp*c, Rn*c, c, 0).
// ---------------------------------------------------------------------------
__global__ __launch_bounds__(256) void k_rv() {
    int idx = blockIdx.x * 256 + threadIdx.x;     // < BN*NH
    float s = psum[idx] + psum[BN * NH + idx]
            + psum[2 * BN * NH + idx] + psum[3 * BN * NH + idx];
    float cc = 1.0f / s;
    int row = idx >> 3, h = idx & 7;
    float Rp = Rbuf[row * 16 + h] * cc;
    float Rn = Rbuf[row * 16 + 8 + h] * cc;
    Rv_glob[idx] = make_float4(Rp, Rn, cc, 0.f);
}

// ---------------------------------------------------------------------------
// K3 (tensor, bf16 m16n8k16 3-term) — identical to R11/R13 (best known).
// ---------------------------------------------------------------------------
#define GSTR 20
struct SmemT {
    uint32_t Gh[2][32][GSTR];   // 5 KB
    uint32_t Gl[2][32][GSTR];   // 5 KB
    float4   Rv_s[2][32];       // 1 KB
};

__device__ __forceinline__ void stageG(SmemT& sm, int buf, int b, int j0,
                                       int h, int t) {
    const int jj = t >> 3;
    const int d0 = (t & 7) * 4;
    float4 gv = __ldg(reinterpret_cast<const float4*>(
        g_buf + (size_t)(b * NN + j0 + jj) * OUTF + h * 32 + d0));
    float vs[4] = {gv.x, gv.y, gv.z, gv.w};
    uint32_t myhi[4], mylo[4];
#pragma unroll
    for (int e = 0; e < 4; e++) {
        __nv_bfloat16 hb = __float2bfloat16(vs[e]);
        float hf = __bfloat162float(hb);
        __nv_bfloat16 lb = __float2bfloat16(vs[e] - hf);
        myhi[e] = (uint32_t)__bfloat16_as_ushort(hb);
        mylo[e] = (uint32_t)__bfloat16_as_ushort(lb);
    }
    const int p = jj >> 1;
    const bool evenj = (jj & 1) == 0;
#pragma unroll
    for (int e = 0; e < 4; e++) {
        uint32_t phi = __shfl_xor_sync(0xffffffffu, myhi[e], 8);
        uint32_t plo = __shfl_xor_sync(0xffffffffu, mylo[e], 8);
        if (evenj) sm.Gh[buf][d0 + e][p] = myhi[e] | (phi << 16);
        else       sm.Gl[buf][d0 + e][p] = plo | (mylo[e] << 16);
    }
}

__device__ __forceinline__ float selw(float Lp, float Ln, float4 rv) {
    float p = Lp * rv.x;
    float q = Ln * rv.y;
    return (p >= rv.z) ? p : q;
}

__global__ __launch_bounds__(256, 3) void k_aggmma(const float* __restrict__ adj,
                                                   float* __restrict__ out) {
    __shared__ SmemT sm;
    const int t = threadIdx.x;
    const int bid = blockIdx.x;
    const int jh = bid >> 8;
    const int b  = (bid >> 6) & 3;
    const int h  = (bid >> 3) & 7;
    const int i0 = (bid & 7) * 128;
    const int jbase = jh * 512;
    float* dst = jh ? p1_buf : out;

    const int lane = t & 31;
    const int gq = lane >> 2, tid4 = lane & 3;
    const int m0 = (t >> 5) * 16;

    const int r0g = b * NN + i0 + m0 + gq;
    const float Lp0 = Lbuf[r0g * 16 + h],       Ln0 = Lbuf[r0g * 16 + 8 + h];
    const float Lp1 = Lbuf[(r0g + 8) * 16 + h], Ln1 = Lbuf[(r0g + 8) * 16 + 8 + h];

    float acc[4][4];
#pragma unroll
    for (int nt = 0; nt < 4; nt++)
#pragma unroll
        for (int c = 0; c < 4; c++) acc[nt][c] = 0.f;

    // prologue
    stageG(sm, 0, b, jbase, h, t);
    if (t < 32)
        sm.Rv_s[0][t] = __ldg(&Rv_glob[(b * NN + jbase + t) * NH + h]);

    const float* arow0 = adj + (size_t)r0g * NN;
    const float* arow1 = arow0 + 8 * NN;

#pragma unroll 1
    for (int n = 0; n < 16; n++) {
        const int j0 = jbase + n * 32;
        const int buf = n & 1;

        // adj prefetch: 4 x LDG.128 (phys cols 4*tid4..+3, +16; rows gq, gq+8)
        float4 aA[2], aB[2];
        aA[0] = __ldg(reinterpret_cast<const float4*>(arow0 + j0 + 4 * tid4));
        aA[1] = __ldg(reinterpret_cast<const float4*>(arow0 + j0 + 16 + 4 * tid4));
        aB[0] = __ldg(reinterpret_cast<const float4*>(arow1 + j0 + 4 * tid4));
        aB[1] = __ldg(reinterpret_cast<const float4*>(arow1 + j0 + 16 + 4 * tid4));

        __syncthreads();   // chunk n's G/Rv visible; prior reads of buf done

        if (n < 15) {
            stageG(sm, buf ^ 1, b, j0 + 32, h, t);
            if (t < 32)
                sm.Rv_s[buf ^ 1][t] =
                    __ldg(&Rv_glob[(b * NN + j0 + 32 + t) * NH + h]);
        }

#pragma unroll
        for (int kg = 0; kg < 2; kg++) {
            float4 rv0 = sm.Rv_s[buf][kg * 16 + 4 * tid4 + 0];
            float4 rv1 = sm.Rv_s[buf][kg * 16 + 4 * tid4 + 1];
            float4 rv2 = sm.Rv_s[buf][kg * 16 + 4 * tid4 + 2];
            float4 rv3 = sm.Rv_s[buf][kg * 16 + 4 * tid4 + 3];
            const float* avA = &aA[kg].x;
            const float* avB = &aB[kg].x;
            float w0 = avA[0] * selw(Lp0, Ln0, rv0);
            float w1 = avA[1] * selw(Lp0, Ln0, rv1);
            float w2 = avA[2] * selw(Lp0, Ln0, rv2);
            float w3 = avA[3] * selw(Lp0, Ln0, rv3);
            float v0 = avB[0] * selw(Lp1, Ln1, rv0);
            float v1 = avB[1] * selw(Lp1, Ln1, rv1);
            float v2 = avB[2] * selw(Lp1, Ln1, rv2);
            float v3 = avB[3] * selw(Lp1, Ln1, rv3);

            __nv_bfloat162 hw01 = __floats2bfloat162_rn(w0, w1);
            __nv_bfloat162 hw23 = __floats2bfloat162_rn(w2, w3);
            __nv_bfloat162 hv01 = __floats2bfloat162_rn(v0, v1);
            __nv_bfloat162 hv23 = __floats2bfloat162_rn(v2, v3);
            __nv_bfloat162 lw01 = __floats2bfloat162_rn(
                w0 - __low2float(hw01), w1 - __high2float(hw01));
            __nv_bfloat162 lw23 = __floats2bfloat162_rn(
                w2 - __low2float(hw23), w3 - __high2float(hw23));
            __nv_bfloat162 lv01 = __floats2bfloat162_rn(
                v0 - __low2float(hv01), v1 - __high2float(hv01));
            __nv_bfloat162 lv23 = __floats2bfloat162_rn(
                v2 - __low2float(hv23), v3 - __high2float(hv23));

            uint32_t ah[4] = {bf2u(hw01), bf2u(hv01), bf2u(hw23), bf2u(hv23)};
            uint32_t al[4] = {bf2u(lw01), bf2u(lv01), bf2u(lw23), bf2u(lv23)};

#pragma unroll
            for (int nt = 0; nt < 4; nt++) {
                int row = nt * 8 + gq;
                int wofs = 8 * kg + 2 * tid4;
                uint2 bh2 = *reinterpret_cast<const uint2*>(&sm.Gh[buf][row][wofs]);
                uint2 bl2 = *reinterpret_cast<const uint2*>(&sm.Gl[buf][row][wofs]);
                uint32_t bh[2] = {bh2.x, bh2.y};
                uint32_t bl[2] = {bl2.x, bl2.y};
                mma_bf16(acc[nt], ah, bh);
                mma_bf16(acc[nt], ah, bl);
                mma_bf16(acc[nt], al, bh);
            }
        }
    }

    // epilogue
#pragma unroll
    for (int nt = 0; nt < 4; nt++) {
        float* op0 = dst + (size_t)r0g * OUTF + h * 32 + nt * 8 + 2 * tid4;
        float* op1 = op0 + 8 * OUTF;
        *reinterpret_cast<float2*>(op0) = make_float2(acc[nt][0], acc[nt][1]);
        *reinterpret_cast<float2*>(op1) = make_float2(acc[nt][2], acc[nt][3]);
    }
}

// ---------------------------------------------------------------------------
// K4: out += p1   (combine j-halves)
// ---------------------------------------------------------------------------
__global__ __launch_bounds__(256) void k_comb(float* __restrict__ out) {
    int idx = blockIdx.x * 256 + threadIdx.x;    // < BN*OUTF/4
    float4* o4 = reinterpret_cast<float4*>(out);
    const float4* p4 = reinterpret_cast<const float4*>(p1_buf);
    float4 a = o4[idx], b = p4[idx];
    o4[idx] = make_float4(a.x + b.x, a.y + b.y, a.z + b.z, a.w + b.w);
}

// ---------------------------------------------------------------------------
extern "C" void kernel_launch(void* const* d_in, const int* in_sizes, int n_in,
                              void* d_out, int out_size) {
    const float* h_in = (const float*)d_in[0];
    const float* adj  = (const float*)d_in[1];
    const float* W    = (const float*)d_in[2];
    const float* aw   = (const float*)d_in[3];
    float* out = (float*)d_out;

    k_gemm<<<256, 256>>>(h_in, W, aw);
    k_c<<<4 * (BB * NN) / 32, 512>>>(adj);
    k_rv<<<BN * NH / 256, 256>>>();
    k_aggmma<<<512, 256>>>(adj, out);
    k_comb<<<BN * OUTF / 4 / 256, 256>>>(out);
}

// round 15
// speedup vs baseline: 1.8207x; 1.1063x over previous
#include <cuda_runtime.h>
#include <cuda_bf16.h>
#include <cstdint>

#define BB 4
#define NN 1024
#define INF 256
#define OUTF 256
#define NH 8
#define BN (BB*NN)

// ---------------- scratch (allocation-free) ----------------
__device__ float g_buf[BN*OUTF];    // g = h @ W  (4 MB)
__device__ float p1_buf[BN*OUTF];   // j-half-1 partial (4 MB)
__device__ float Lbuf[BN*16];       // [exp(el) x8, exp(.2el) x8]
__device__ float Rbuf[BN*16];       // [exp(er) x8, exp(.2er) x8]
__device__ float4 Rv_glob[BN*NH];   // (Rp*c, Rn*c, c, 0) per (b,j,h)
__device__ float psum[4*BN*NH];     // k_c partial sums (i-quarters)

__device__ __forceinline__ uint32_t bf2u(__nv_bfloat162 v) {
    return *reinterpret_cast<uint32_t*>(&v);
}
__device__ __forceinline__ void mma_bf16(float* d, const uint32_t* a,
                                         const uint32_t* b) {
    asm volatile(
        "mma.sync.aligned.m16n8k16.row.col.f32.bf16.bf16.f32 "
        "{%0,%1,%2,%3}, {%4,%5,%6,%7}, {%8,%9}, {%0,%1,%2,%3};"
        : "+f"(d[0]), "+f"(d[1]), "+f"(d[2]), "+f"(d[3])
        : "r"(a[0]), "r"(a[1]), "r"(a[2]), "r"(a[3]), "r"(b[0]), "r"(b[1]));
}

// split a float pair into bf16x2 hi + lo words
__device__ __forceinline__ void split2(float a0, float a1,
                                       uint32_t& hi, uint32_t& lo) {
    __nv_bfloat162 h = __floats2bfloat162_rn(a0, a1);
    __nv_bfloat162 l = __floats2bfloat162_rn(a0 - __low2float(h),
                                             a1 - __high2float(h));
    hi = bf2u(h); lo = bf2u(l);
}

// ---------------------------------------------------------------------------
// K1 (tensor): g = X @ W via bf16 m16n8k16 3-term, fused el/er+exp epilogue.
// Grid 256 = (rb: 64-row tile) x (cb: 64-col tile = 2 heads). 256 thr = 8
// warps: warp w = rows (w&3)*16, head-half w>>2 (32 cols = 1 head).
// A fragments straight from gmem (LDG.128 per row); B staged in smem,
// k-pair-major [8][68] (frag LDS conflict-free).
// ---------------------------------------------------------------------------
__global__ __launch_bounds__(256) void k_gemm(const float* __restrict__ X,
                                              const float* __restrict__ W,
                                              const float* __restrict__ aw) {
    __shared__ uint32_t Bh[8][68];
    __shared__ uint32_t Bl[8][68];
    const int t = threadIdx.x;
    const int rb = blockIdx.x >> 2, cb = blockIdx.x & 3;
    const int lane = t & 31, w = t >> 5;
    const int gq = lane >> 2, t4 = lane & 3;
    const int wr = w & 3;        // row group
    const int wh = w >> 2;       // head half (0/1)
    const int grow0 = rb * 64 + wr * 16 + gq;

    // staging roles
    const int kk = t >> 4;            // 0..15 (k row within tile)
    const int nb = (t & 15) * 4;      // 4 consecutive n
    const bool evenk = (kk & 1) == 0;
    const int pidx = kk >> 1;

    float acc[4][4];
#pragma unroll
    for (int nt = 0; nt < 4; nt++)
#pragma unroll
        for (int c = 0; c < 4; c++) acc[nt][c] = 0.f;

    const float* xrow0 = X + (size_t)grow0 * INF;
    const float* xrow1 = xrow0 + 8 * INF;

    // prologue loads
    float4 wv = __ldg(reinterpret_cast<const float4*>(
        &W[kk * OUTF + cb * 64 + nb]));
    float4 xa = __ldg(reinterpret_cast<const float4*>(xrow0 + 4 * t4));
    float4 xb = __ldg(reinterpret_cast<const float4*>(xrow1 + 4 * t4));

    for (int k0 = 0; k0 < INF; k0 += 16) {
        __syncthreads();   // previous iter's B reads done
        {
            float pw[4] = {wv.x, wv.y, wv.z, wv.w};
            float qw[4];
#pragma unroll
            for (int e = 0; e < 4; e++)
                qw[e] = __shfl_xor_sync(0xffffffffu, pw[e], 16);
#pragma unroll
            for (int e = 0; e < 4; e++) {
                float a0 = evenk ? pw[e] : qw[e];   // even-k value
                float a1 = evenk ? qw[e] : pw[e];   // odd-k value
                __nv_bfloat162 h = __floats2bfloat162_rn(a0, a1);
                if (evenk) {
                    Bh[pidx][nb + e] = bf2u(h);
                } else {
                    __nv_bfloat162 l = __floats2bfloat162_rn(
                        a0 - __low2float(h), a1 - __high2float(h));
                    Bl[pidx][nb + e] = bf2u(l);
                }
            }
        }
        __syncthreads();

        if (k0 + 16 < INF)
            wv = __ldg(reinterpret_cast<const float4*>(
                &W[(k0 + 16 + kk) * OUTF + cb * 64 + nb]));

        // A fragments (registers, no smem)
        uint32_t ah[4], al[4];
        split2(xa.x, xa.y, ah[0], al[0]);
        split2(xb.x, xb.y, ah[1], al[1]);
        split2(xa.z, xa.w, ah[2], al[2]);
        split2(xb.z, xb.w, ah[3], al[3]);

        if (k0 + 16 < INF) {
            xa = __ldg(reinterpret_cast<const float4*>(xrow0 + k0 + 16 + 4 * t4));
            xb = __ldg(reinterpret_cast<const float4*>(xrow1 + k0 + 16 + 4 * t4));
        }

#pragma unroll
        for (int nt = 0; nt < 4; nt++) {
            int n = wh * 32 + nt * 8 + gq;
            uint32_t bh[2] = {Bh[2 * t4][n], Bh[2 * t4 + 1][n]};
            uint32_t bl[2] = {Bl[2 * t4][n], Bl[2 * t4 + 1][n]};
            mma_bf16(acc[nt], ah, bh);
            mma_bf16(acc[nt], ah, bl);
            mma_bf16(acc[nt], al, bh);
        }
    }

    // ---- epilogue: write g, compute el/er, exp in place ----
    const int head = cb * 2 + wh;
    float e_l[2] = {0.f, 0.f}, e_r[2] = {0.f, 0.f};
#pragma unroll
    for (int nt = 0; nt < 4; nt++) {
        int d0 = nt * 8 + 2 * t4;
        float wl0 = __ldg(&aw[d0]),      wl1 = __ldg(&aw[d0 + 1]);
        float wr0 = __ldg(&aw[32 + d0]), wr1 = __ldg(&aw[32 + d0 + 1]);
        e_l[0] += acc[nt][0] * wl0 + acc[nt][1] * wl1;
        e_l[1] += acc[nt][2] * wl0 + acc[nt][3] * wl1;
        e_r[0] += acc[nt][0] * wr0 + acc[nt][1] * wr1;
        e_r[1] += acc[nt][2] * wr0 + acc[nt][3] * wr1;

        float* gp0 = g_buf + (size_t)grow0 * OUTF + cb * 64 + wh * 32 + d0;
        *reinterpret_cast<float2*>(gp0) = make_float2(acc[nt][0], acc[nt][1]);
        *reinterpret_cast<float2*>(gp0 + 8 * OUTF) =
            make_float2(acc[nt][2], acc[nt][3]);
    }
#pragma unroll
    for (int rh = 0; rh < 2; rh++) {
        e_l[rh] += __shfl_xor_sync(0xffffffffu, e_l[rh], 1);
        e_l[rh] += __shfl_xor_sync(0xffffffffu, e_l[rh], 2);
        e_r[rh] += __shfl_xor_sync(0xffffffffu, e_r[rh], 1);
        e_r[rh] += __shfl_xor_sync(0xffffffffu, e_r[rh], 2);
    }
    if (t4 == 0) {
#pragma unroll
        for (int rh = 0; rh < 2; rh++) {
            int row = grow0 + rh * 8;
            Lbuf[row * 16 + head]     = __expf(e_l[rh]);
            Lbuf[row * 16 + 8 + head] = __expf(0.2f * e_l[rh]);
            Rbuf[row * 16 + head]     = __expf(e_r[rh]);
            Rbuf[row * 16 + 8 + head] = __expf(0.2f * e_r[rh]);
        }
    }
}

// ---------------------------------------------------------------------------
// K2: partial column sums over one i-quarter. Grid 512 = (iq, b, j-chunk).
// ---------------------------------------------------------------------------
__global__ __launch_bounds__(512) void k_c(const float* __restrict__ adj) {
    __shared__ float ssum[16][32][8];
    const int t = threadIdx.x;
    const int iq = blockIdx.x >> 7;
    const int b = (blockIdx.x >> 5) & 3;
    const int j0 = (blockIdx.x & 31) * 32;
    const int jl = t & 31, ig = t >> 5;

    const float4* rrow = reinterpret_cast<const float4*>(&Rbuf[(b * NN + j0 + jl) * 16]);
    float4 rp0 = rrow[0], rp1 = rrow[1], rn0 = rrow[2], rn1 = rrow[3];
    float EPr[8] = {rp0.x, rp0.y, rp0.z, rp0.w, rp1.x, rp1.y, rp1.z, rp1.w};
    float ENr[8] = {rn0.x, rn0.y, rn0.z, rn0.w, rn1.x, rn1.y, rn1.z, rn1.w};

    float acc[8];
#pragma unroll
    for (int h = 0; h < 8; h++) acc[h] = 0.f;

    const int ibeg = iq * 256;
    const float* adjcol = adj + (size_t)b * NN * NN + j0 + jl;
#pragma unroll 4
    for (int i = ibeg + ig; i < ibeg + 256; i += 16) {
        float a = __ldg(adjcol + (size_t)i * NN);
        const float4* lr = reinterpret_cast<const float4*>(&Lbuf[(b * NN + i) * 16]);
        float4 lp0 = __ldg(&lr[0]), lp1 = __ldg(&lr[1]);
        float4 ln0 = __ldg(&lr[2]), ln1 = __ldg(&lr[3]);
        float EPl[8] = {lp0.x, lp0.y, lp0.z, lp0.w, lp1.x, lp1.y, lp1.z, lp1.w};
        float ENl[8] = {ln0.x, ln0.y, ln0.z, ln0.w, ln1.x, ln1.y, ln1.z, ln1.w};
#pragma unroll
        for (int h = 0; h < 8; h++) {
            float p = EPl[h] * EPr[h];
            float q = ENl[h] * ENr[h];
            float w = (p >= 1.0f) ? p : q;
            acc[h] = fmaf(a, w, acc[h]);
        }
    }
#pragma unroll
    for (int h = 0; h < 8; h++) ssum[ig][jl][h] = acc[h];
    __syncthreads();

    if (t < 256) {
        int jl2 = t >> 3, h = t & 7;
        float s = 0.f;
#pragma unroll
        for (int g = 0; g < 16; g++) s += ssum[g][jl2][h];
        psum[iq * BN * NH + (b * NN + j0 + jl2) * NH + h] = s;
    }
}

// ---------------------------------------------------------------------------
// K_rv: combine i-quarter partials -> Rv_glob = (Rp*c, Rn*c, c, 0).
// ---------------------------------------------------------------------------
__global__ __launch_bounds__(256) void k_rv() {
    int idx = blockIdx.x * 256 + threadIdx.x;     // < BN*NH
    float s = psum[idx] + psum[BN * NH + idx]
            + psum[2 * BN * NH + idx] + psum[3 * BN * NH + idx];
    float cc = 1.0f / s;
    int row = idx >> 3, h = idx & 7;
    float Rp = Rbuf[row * 16 + h] * cc;
    float Rn = Rbuf[row * 16 + 8 + h] * cc;
    Rv_glob[idx] = make_float4(Rp, Rn, cc, 0.f);
}

// ---------------------------------------------------------------------------
// K3 (tensor, bf16 m16n8k16 3-term) — identical to R11/R13/R14 (best known).
// ---------------------------------------------------------------------------
#define GSTR 20
struct SmemT {
    uint32_t Gh[2][32][GSTR];   // 5 KB
    uint32_t Gl[2][32][GSTR];   // 5 KB
    float4   Rv_s[2][32];       // 1 KB
};

__device__ __forceinline__ void stageG(SmemT& sm, int buf, int b, int j0,
                                       int h, int t) {
    const int jj = t >> 3;
    const int d0 = (t & 7) * 4;
    float4 gv = __ldg(reinterpret_cast<const float4*>(
        g_buf + (size_t)(b * NN + j0 + jj) * OUTF + h * 32 + d0));
    float vs[4] = {gv.x, gv.y, gv.z, gv.w};
    uint32_t myhi[4], mylo[4];
#pragma unroll
    for (int e = 0; e < 4; e++) {
        __nv_bfloat16 hb = __float2bfloat16(vs[e]);
        float hf = __bfloat162float(hb);
        __nv_bfloat16 lb = __float2bfloat16(vs[e] - hf);
        myhi[e] = (uint32_t)__bfloat16_as_ushort(hb);
        mylo[e] = (uint32_t)__bfloat16_as_ushort(lb);
    }
    const int p = jj >> 1;
    const bool evenj = (jj & 1) == 0;
#pragma unroll
    for (int e = 0; e < 4; e++) {
        uint32_t phi = __shfl_xor_sync(0xffffffffu, myhi[e], 8);
        uint32_t plo = __shfl_xor_sync(0xffffffffu, mylo[e], 8);
        if (evenj) sm.Gh[buf][d0 + e][p] = myhi[e] | (phi << 16);
        else       sm.Gl[buf][d0 + e][p] = plo | (mylo[e] << 16);
    }
}

__device__ __forceinline__ float selw(float Lp, float Ln, float4 rv) {
    float p = Lp * rv.x;
    float q = Ln * rv.y;
    return (p >= rv.z) ? p : q;
}

__global__ __launch_bounds__(256, 3) void k_aggmma(const float* __restrict__ adj,
                                                   float* __restrict__ out) {
    __shared__ SmemT sm;
    const int t = threadIdx.x;
    const int bid = blockIdx.x;
    const int jh = bid >> 8;
    const int b  = (bid >> 6) & 3;
    const int h  = (bid >> 3) & 7;
    const int i0 = (bid & 7) * 128;
    const int jbase = jh * 512;
    float* dst = jh ? p1_buf : out;

    const int lane = t & 31;
    const int gq = lane >> 2, tid4 = lane & 3;
    const int m0 = (t >> 5) * 16;

    const int r0g = b * NN + i0 + m0 + gq;
    const float Lp0 = Lbuf[r0g * 16 + h],       Ln0 = Lbuf[r0g * 16 + 8 + h];
    const float Lp1 = Lbuf[(r0g + 8) * 16 + h], Ln1 = Lbuf[(r0g + 8) * 16 + 8 + h];

    float acc[4][4];
#pragma unroll
    for (int nt = 0; nt < 4; nt++)
#pragma unroll
        for (int c = 0; c < 4; c++) acc[nt][c] = 0.f;

    // prologue
    stageG(sm, 0, b, jbase, h, t);
    if (t < 32)
        sm.Rv_s[0][t] = __ldg(&Rv_glob[(b * NN + jbase + t) * NH + h]);

    const float* arow0 = adj + (size_t)r0g * NN;
    const float* arow1 = arow0 + 8 * NN;

#pragma unroll 1
    for (int n = 0; n < 16; n++) {
        const int j0 = jbase + n * 32;
        const int buf = n & 1;

        float4 aA[2], aB[2];
        aA[0] = __ldg(reinterpret_cast<const float4*>(arow0 + j0 + 4 * tid4));
        aA[1] = __ldg(reinterpret_cast<const float4*>(arow0 + j0 + 16 + 4 * tid4));
        aB[0] = __ldg(reinterpret_cast<const float4*>(arow1 + j0 + 4 * tid4));
        aB[1] = __ldg(reinterpret_cast<const float4*>(arow1 + j0 + 16 + 4 * tid4));

        __syncthreads();

        if (n < 15) {
            stageG(sm, buf ^ 1, b, j0 + 32, h, t);
            if (t < 32)
                sm.Rv_s[buf ^ 1][t] =
                    __ldg(&Rv_glob[(b * NN + j0 + 32 + t) * NH + h]);
        }

#pragma unroll
        for (int kg = 0; kg < 2; kg++) {
            float4 rv0 = sm.Rv_s[buf][kg * 16 + 4 * tid4 + 0];
            float4 rv1 = sm.Rv_s[buf][kg * 16 + 4 * tid4 + 1];
            float4 rv2 = sm.Rv_s[buf][kg * 16 + 4 * tid4 + 2];
            float4 rv3 = sm.Rv_s[buf][kg * 16 + 4 * tid4 + 3];
            const float* avA = &aA[kg].x;
            const float* avB = &aB[kg].x;
            float w0 = avA[0] * selw(Lp0, Ln0, rv0);
            float w1 = avA[1] * selw(Lp0, Ln0, rv1);
            float w2 = avA[2] * selw(Lp0, Ln0, rv2);
            float w3 = avA[3] * selw(Lp0, Ln0, rv3);
            float v0 = avB[0] * selw(Lp1, Ln1, rv0);
            float v1 = avB[1] * selw(Lp1, Ln1, rv1);
            float v2 = avB[2] * selw(Lp1, Ln1, rv2);
            float v3 = avB[3] * selw(Lp1, Ln1, rv3);

            __nv_bfloat162 hw01 = __floats2bfloat162_rn(w0, w1);
            __nv_bfloat162 hw23 = __floats2bfloat162_rn(w2, w3);
            __nv_bfloat162 hv01 = __floats2bfloat162_rn(v0, v1);
            __nv_bfloat162 hv23 = __floats2bfloat162_rn(v2, v3);
            __nv_bfloat162 lw01 = __floats2bfloat162_rn(
                w0 - __low2float(hw01), w1 - __high2float(hw01));
            __nv_bfloat162 lw23 = __floats2bfloat162_rn(
                w2 - __low2float(hw23), w3 - __high2float(hw23));
            __nv_bfloat162 lv01 = __floats2bfloat162_rn(
                v0 - __low2float(hv01), v1 - __high2float(hv01));
            __nv_bfloat162 lv23 = __floats2bfloat162_rn(
                v2 - __low2float(hv23), v3 - __high2float(hv23));

            uint32_t ah[4] = {bf2u(hw01), bf2u(hv01), bf2u(hw23), bf2u(hv23)};
            uint32_t al[4] = {bf2u(lw01), bf2u(lv01), bf2u(lw23), bf2u(lv23)};

#pragma unroll
            for (int nt = 0; nt < 4; nt++) {
                int row = nt * 8 + gq;
                int wofs = 8 * kg + 2 * tid4;
                uint2 bh2 = *reinterpret_cast<const uint2*>(&sm.Gh[buf][row][wofs]);
                uint2 bl2 = *reinterpret_cast<const uint2*>(&sm.Gl[buf][row][wofs]);
                uint32_t bh[2] = {bh2.x, bh2.y};
                uint32_t bl[2] = {bl2.x, bl2.y};
                mma_bf16(acc[nt], ah, bh);
                mma_bf16(acc[nt], ah, bl);
                mma_bf16(acc[nt], al, bh);
            }
        }
    }

    // epilogue
#pragma unroll
    for (int nt = 0; nt < 4; nt++) {
        float* op0 = dst + (size_t)r0g * OUTF + h * 32 + nt * 8 + 2 * tid4;
        float* op1 = op0 + 8 * OUTF;
        *reinterpret_cast<float2*>(op0) = make_float2(acc[nt][0], acc[nt][1]);
        *reinterpret_cast<float2*>(op1) = make_float2(acc[nt][2], acc[nt][3]);
    }
}

// ---------------------------------------------------------------------------
// K4: out += p1   (combine j-halves)
// ---------------------------------------------------------------------------
__global__ __launch_bounds__(256) void k_comb(float* __restrict__ out) {
    int idx = blockIdx.x * 256 + threadIdx.x;    // < BN*OUTF/4
    float4* o4 = reinterpret_cast<float4*>(out);
    const float4* p4 = reinterpret_cast<const float4*>(p1_buf);
    float4 a = o4[idx], b = p4[idx];
    o4[idx] = make_float4(a.x + b.x, a.y + b.y, a.z + b.z, a.w + b.w);
}

// ---------------------------------------------------------------------------
extern "C" void kernel_launch(void* const* d_in, const int* in_sizes, int n_in,
                              void* d_out, int out_size) {
    const float* h_in = (const float*)d_in[0];
    const float* adj  = (const float*)d_in[1];
    const float* W    = (const float*)d_in[2];
    const float* aw   = (const float*)d_in[3];
    float* out = (float*)d_out;

    k_gemm<<<256, 256>>>(h_in, W, aw);
    k_c<<<4 * (BB * NN) / 32, 512>>>(adj);
    k_rv<<<BN * NH / 256, 256>>>();
    k_aggmma<<<512, 256>>>(adj, out);
    k_comb<<<BN * OUTF / 4 / 256, 256>>>(out);
}

// round 16
// speedup vs baseline: 1.9050x; 1.0463x over previous
#include <cuda_runtime.h>
#include <cuda_bf16.h>
#include <cstdint>

#define BB 4
#define NN 1024
#define INF 256
#define OUTF 256
#define NH 8
#define BN (BB*NN)

// ---------------- scratch (allocation-free) ----------------
__device__ float g_buf[BN*OUTF];    // g = h @ W  (4 MB)
__device__ float p1_buf[BN*OUTF];   // j-half-1 partial (4 MB)
__device__ float Lbuf[BN*16];       // [exp(el) x8, exp(.2el) x8]
__device__ float Rbuf[BN*16];       // [exp(er) x8, exp(.2er) x8]
__device__ float4 Rv_glob[BN*NH];   // (Rp*c, Rn*c, c, 0) per (b,j,h)
__device__ float psum[4*BN*NH];     // k_c partial sums (i-quarters)
__device__ __align__(16) uint32_t Gpk_hi[BN*OUTF/2];  // packed bf16 pairs (2 MB)
__device__ __align__(16) uint32_t Gpk_lo[BN*OUTF/2];  // lo corrections   (2 MB)

__device__ __forceinline__ uint32_t bf2u(__nv_bfloat162 v) {
    return *reinterpret_cast<uint32_t*>(&v);
}
__device__ __forceinline__ void mma_bf16(float* d, const uint32_t* a,
                                         const uint32_t* b) {
    asm volatile(
        "mma.sync.aligned.m16n8k16.row.col.f32.bf16.bf16.f32 "
        "{%0,%1,%2,%3}, {%4,%5,%6,%7}, {%8,%9}, {%0,%1,%2,%3};"
        : "+f"(d[0]), "+f"(d[1]), "+f"(d[2]), "+f"(d[3])
        : "r"(a[0]), "r"(a[1]), "r"(a[2]), "r"(a[3]), "r"(b[0]), "r"(b[1]));
}

// split a float pair into bf16x2 hi + lo words
__device__ __forceinline__ void split2(float a0, float a1,
                                       uint32_t& hi, uint32_t& lo) {
    __nv_bfloat162 h = __floats2bfloat162_rn(a0, a1);
    __nv_bfloat162 l = __floats2bfloat162_rn(a0 - __low2float(h),
                                             a1 - __high2float(h));
    hi = bf2u(h); lo = bf2u(l);
}

// ---------------------------------------------------------------------------
// K1 (tensor): g = X @ W via bf16 m16n8k16 3-term, fused el/er+exp epilogue.
// (identical to R15)
// ---------------------------------------------------------------------------
__global__ __launch_bounds__(256) void k_gemm(const float* __restrict__ X,
                                              const float* __restrict__ W,
                                              const float* __restrict__ aw) {
    __shared__ uint32_t Bh[8][68];
    __shared__ uint32_t Bl[8][68];
    const int t = threadIdx.x;
    const int rb = blockIdx.x >> 2, cb = blockIdx.x & 3;
    const int lane = t & 31, w = t >> 5;
    const int gq = lane >> 2, t4 = lane & 3;
    const int wr = w & 3;
    const int wh = w >> 2;
    const int grow0 = rb * 64 + wr * 16 + gq;

    const int kk = t >> 4;
    const int nb = (t & 15) * 4;
    const bool evenk = (kk & 1) == 0;
    const int pidx = kk >> 1;

    float acc[4][4];
#pragma unroll
    for (int nt = 0; nt < 4; nt++)
#pragma unroll
        for (int c = 0; c < 4; c++) acc[nt][c] = 0.f;

    const float* xrow0 = X + (size_t)grow0 * INF;
    const float* xrow1 = xrow0 + 8 * INF;

    float4 wv = __ldg(reinterpret_cast<const float4*>(
        &W[kk * OUTF + cb * 64 + nb]));
    float4 xa = __ldg(reinterpret_cast<const float4*>(xrow0 + 4 * t4));
    float4 xb = __ldg(reinterpret_cast<const float4*>(xrow1 + 4 * t4));

    for (int k0 = 0; k0 < INF; k0 += 16) {
        __syncthreads();
        {
            float pw[4] = {wv.x, wv.y, wv.z, wv.w};
            float qw[4];
#pragma unroll
            for (int e = 0; e < 4; e++)
                qw[e] = __shfl_xor_sync(0xffffffffu, pw[e], 16);
#pragma unroll
            for (int e = 0; e < 4; e++) {
                float a0 = evenk ? pw[e] : qw[e];
                float a1 = evenk ? qw[e] : pw[e];
                __nv_bfloat162 h = __floats2bfloat162_rn(a0, a1);
                if (evenk) {
                    Bh[pidx][nb + e] = bf2u(h);
                } else {
                    __nv_bfloat162 l = __floats2bfloat162_rn(
                        a0 - __low2float(h), a1 - __high2float(h));
                    Bl[pidx][nb + e] = bf2u(l);
                }
            }
        }
        __syncthreads();

        if (k0 + 16 < INF)
            wv = __ldg(reinterpret_cast<const float4*>(
                &W[(k0 + 16 + kk) * OUTF + cb * 64 + nb]));

        uint32_t ah[4], al[4];
        split2(xa.x, xa.y, ah[0], al[0]);
        split2(xb.x, xb.y, ah[1], al[1]);
        split2(xa.z, xa.w, ah[2], al[2]);
        split2(xb.z, xb.w, ah[3], al[3]);

        if (k0 + 16 < INF) {
            xa = __ldg(reinterpret_cast<const float4*>(xrow0 + k0 + 16 + 4 * t4));
            xb = __ldg(reinterpret_cast<const float4*>(xrow1 + k0 + 16 + 4 * t4));
        }

#pragma unroll
        for (int nt = 0; nt < 4; nt++) {
            int n = wh * 32 + nt * 8 + gq;
            uint32_t bh[2] = {Bh[2 * t4][n], Bh[2 * t4 + 1][n]};
            uint32_t bl[2] = {Bl[2 * t4][n], Bl[2 * t4 + 1][n]};
            mma_bf16(acc[nt], ah, bh);
            mma_bf16(acc[nt], ah, bl);
            mma_bf16(acc[nt], al, bh);
        }
    }

    const int head = cb * 2 + wh;
    float e_l[2] = {0.f, 0.f}, e_r[2] = {0.f, 0.f};
#pragma unroll
    for (int nt = 0; nt < 4; nt++) {
        int d0 = nt * 8 + 2 * t4;
        float wl0 = __ldg(&aw[d0]),      wl1 = __ldg(&aw[d0 + 1]);
        float wr0 = __ldg(&aw[32 + d0]), wr1 = __ldg(&aw[32 + d0 + 1]);
        e_l[0] += acc[nt][0] * wl0 + acc[nt][1] * wl1;
        e_l[1] += acc[nt][2] * wl0 + acc[nt][3] * wl1;
        e_r[0] += acc[nt][0] * wr0 + acc[nt][1] * wr1;
        e_r[1] += acc[nt][2] * wr0 + acc[nt][3] * wr1;

        float* gp0 = g_buf + (size_t)grow0 * OUTF + cb * 64 + wh * 32 + d0;
        *reinterpret_cast<float2*>(gp0) = make_float2(acc[nt][0], acc[nt][1]);
        *reinterpret_cast<float2*>(gp0 + 8 * OUTF) =
            make_float2(acc[nt][2], acc[nt][3]);
    }
#pragma unroll
    for (int rh = 0; rh < 2; rh++) {
        e_l[rh] += __shfl_xor_sync(0xffffffffu, e_l[rh], 1);
        e_l[rh] += __shfl_xor_sync(0xffffffffu, e_l[rh], 2);
        e_r[rh] += __shfl_xor_sync(0xffffffffu, e_r[rh], 1);
        e_r[rh] += __shfl_xor_sync(0xffffffffu, e_r[rh], 2);
    }
    if (t4 == 0) {
#pragma unroll
        for (int rh = 0; rh < 2; rh++) {
            int row = grow0 + rh * 8;
            Lbuf[row * 16 + head]     = __expf(e_l[rh]);
            Lbuf[row * 16 + 8 + head] = __expf(0.2f * e_l[rh]);
            Rbuf[row * 16 + head]     = __expf(e_r[rh]);
            Rbuf[row * 16 + 8 + head] = __expf(0.2f * e_r[rh]);
        }
    }
}

// ---------------------------------------------------------------------------
// K_gpack: g -> packed bf16 hi/lo pair-words, per (b,h,jc):
// word[((b*8+h)*32+jc)*512 + d*16 + p] = (bf16(g[2p]), bf16(g[2p+1])) @ dim d
// (verified correct in R12)
// ---------------------------------------------------------------------------
__global__ __launch_bounds__(256) void k_gpack() {
    __shared__ float gs[32][264];
    const int t = threadIdx.x;
    const int b = blockIdx.x >> 5, jc = blockIdx.x & 31;

    const float4* src = reinterpret_cast<const float4*>(
        g_buf + (size_t)(b * NN + jc * 32) * OUTF);
#pragma unroll
    for (int m = 0; m < 8; m++) {
        int v = t + m * 256;
        int row = v >> 6, c4 = v & 63;
        float4 x = src[(size_t)row * 64 + c4];
        *reinterpret_cast<float4*>(&gs[row][c4 * 4]) = x;
    }
    __syncthreads();

    const int h = t >> 5, d = t & 31;
    uint32_t wh[16], wl[16];
#pragma unroll
    for (int p = 0; p < 16; p++) {
        float a  = gs[2 * p][h * 32 + d];
        float bf = gs[2 * p + 1][h * 32 + d];
        __nv_bfloat16 ha = __float2bfloat16(a);
        __nv_bfloat16 hb = __float2bfloat16(bf);
        __nv_bfloat16 la = __float2bfloat16(a - __bfloat162float(ha));
        __nv_bfloat16 lb = __float2bfloat16(bf - __bfloat162float(hb));
        wh[p] = (uint32_t)__bfloat16_as_ushort(ha) |
                ((uint32_t)__bfloat16_as_ushort(hb) << 16);
        wl[p] = (uint32_t)__bfloat16_as_ushort(la) |
                ((uint32_t)__bfloat16_as_ushort(lb) << 16);
    }
    size_t base = ((size_t)((b * 8 + h) * 32 + jc) << 9) + d * 16;
#pragma unroll
    for (int q = 0; q < 4; q++) {
        *reinterpret_cast<uint4*>(&Gpk_hi[base + 4 * q]) =
            make_uint4(wh[4*q], wh[4*q+1], wh[4*q+2], wh[4*q+3]);
        *reinterpret_cast<uint4*>(&Gpk_lo[base + 4 * q]) =
            make_uint4(wl[4*q], wl[4*q+1], wl[4*q+2], wl[4*q+3]);
    }
}

// ---------------------------------------------------------------------------
// K2: partial column sums over one i-quarter. Grid 512 = (iq, b, j-chunk).
// ---------------------------------------------------------------------------
__global__ __launch_bounds__(512) void k_c(const float* __restrict__ adj) {
    __shared__ float ssum[16][32][8];
    const int t = threadIdx.x;
    const int iq = blockIdx.x >> 7;
    const int b = (blockIdx.x >> 5) & 3;
    const int j0 = (blockIdx.x & 31) * 32;
    const int jl = t & 31, ig = t >> 5;

    const float4* rrow = reinterpret_cast<const float4*>(&Rbuf[(b * NN + j0 + jl) * 16]);
    float4 rp0 = rrow[0], rp1 = rrow[1], rn0 = rrow[2], rn1 = rrow[3];
    float EPr[8] = {rp0.x, rp0.y, rp0.z, rp0.w, rp1.x, rp1.y, rp1.z, rp1.w};
    float ENr[8] = {rn0.x, rn0.y, rn0.z, rn0.w, rn1.x, rn1.y, rn1.z, rn1.w};

    float acc[8];
#pragma unroll
    for (int h = 0; h < 8; h++) acc[h] = 0.f;

    const int ibeg = iq * 256;
    const float* adjcol = adj + (size_t)b * NN * NN + j0 + jl;
#pragma unroll 4
    for (int i = ibeg + ig; i < ibeg + 256; i += 16) {
        float a = __ldg(adjcol + (size_t)i * NN);
        const float4* lr = reinterpret_cast<const float4*>(&Lbuf[(b * NN + i) * 16]);
        float4 lp0 = __ldg(&lr[0]), lp1 = __ldg(&lr[1]);
        float4 ln0 = __ldg(&lr[2]), ln1 = __ldg(&lr[3]);
        float EPl[8] = {lp0.x, lp0.y, lp0.z, lp0.w, lp1.x, lp1.y, lp1.z, lp1.w};
        float ENl[8] = {ln0.x, ln0.y, ln0.z, ln0.w, ln1.x, ln1.y, ln1.z, ln1.w};
#pragma unroll
        for (int h = 0; h < 8; h++) {
            float p = EPl[h] * EPr[h];
            float q = ENl[h] * ENr[h];
            float w = (p >= 1.0f) ? p : q;
            acc[h] = fmaf(a, w, acc[h]);
        }
    }
#pragma unroll
    for (int h = 0; h < 8; h++) ssum[ig][jl][h] = acc[h];
    __syncthreads();

    if (t < 256) {
        int jl2 = t >> 3, h = t & 7;
        float s = 0.f;
#pragma unroll
        for (int g = 0; g < 16; g++) s += ssum[g][jl2][h];
        psum[iq * BN * NH + (b * NN + j0 + jl2) * NH + h] = s;
    }
}

// ---------------------------------------------------------------------------
// K_rv: combine i-quarter partials -> Rv_glob = (Rp*c, Rn*c, c, 0).
// ---------------------------------------------------------------------------
__global__ __launch_bounds__(256) void k_rv() {
    int idx = blockIdx.x * 256 + threadIdx.x;     // < BN*NH
    float s = psum[idx] + psum[BN * NH + idx]
            + psum[2 * BN * NH + idx] + psum[3 * BN * NH + idx];
    float cc = 1.0f / s;
    int row = idx >> 3, h = idx & 7;
    float Rp = Rbuf[row * 16 + h] * cc;
    float Rn = Rbuf[row * 16 + 8 + h] * cc;
    Rv_glob[idx] = make_float4(Rp, Rn, cc, 0.f);
}

// ---------------------------------------------------------------------------
// K3 (tensor, bf16 m16n8k16 3-term): same as R15 EXCEPT stageG is now a
// pure copy from Gpk (cvt/shfl chains removed from the hot loop).
// ---------------------------------------------------------------------------
#define GSTR 20
struct SmemT {
    uint32_t Gh[2][32][GSTR];   // 5 KB
    uint32_t Gl[2][32][GSTR];   // 5 KB
    float4   Rv_s[2][32];       // 1 KB
};

__device__ __forceinline__ void stageG(SmemT& sm, int buf, int b, int jc,
                                       int h, int t) {
    const uint32_t* src = (t < 128 ? Gpk_hi : Gpk_lo) +
                          ((size_t)((b * 8 + h) * 32 + jc) << 9);
    int tt = t & 127;
    uint4 v = __ldg(reinterpret_cast<const uint4*>(src) + tt);
    int d = tt >> 2, w0 = (tt & 3) * 4;
    uint32_t* dstrow = (t < 128 ? sm.Gh[buf][d] : sm.Gl[buf][d]);
    *reinterpret_cast<uint4*>(&dstrow[w0]) = v;
}

__device__ __forceinline__ float selw(float Lp, float Ln, float4 rv) {
    float p = Lp * rv.x;
    float q = Ln * rv.y;
    return (p >= rv.z) ? p : q;
}

__global__ __launch_bounds__(256, 3) void k_aggmma(const float* __restrict__ adj,
                                                   float* __restrict__ out) {
    __shared__ SmemT sm;
    const int t = threadIdx.x;
    const int bid = blockIdx.x;
    const int jh = bid >> 8;
    const int b  = (bid >> 6) & 3;
    const int h  = (bid >> 3) & 7;
    const int i0 = (bid & 7) * 128;
    const int jbase = jh * 512;
    float* dst = jh ? p1_buf : out;

    const int lane = t & 31;
    const int gq = lane >> 2, tid4 = lane & 3;
    const int m0 = (t >> 5) * 16;

    const int r0g = b * NN + i0 + m0 + gq;
    const float Lp0 = Lbuf[r0g * 16 + h],       Ln0 = Lbuf[r0g * 16 + 8 + h];
    const float Lp1 = Lbuf[(r0g + 8) * 16 + h], Ln1 = Lbuf[(r0g + 8) * 16 + 8 + h];

    float acc[4][4];
#pragma unroll
    for (int nt = 0; nt < 4; nt++)
#pragma unroll
        for (int c = 0; c < 4; c++) acc[nt][c] = 0.f;

    // prologue
    stageG(sm, 0, b, jh * 16, h, t);
    if (t < 32)
        sm.Rv_s[0][t] = __ldg(&Rv_glob[(b * NN + jbase + t) * NH + h]);

    const float* arow0 = adj + (size_t)r0g * NN;
    const float* arow1 = arow0 + 8 * NN;

#pragma unroll 1
    for (int n = 0; n < 16; n++) {
        const int j0 = jbase + n * 32;
        const int jc = jh * 16 + n;
        const int buf = n & 1;

        float4 aA[2], aB[2];
        aA[0] = __ldg(reinterpret_cast<const float4*>(arow0 + j0 + 4 * tid4));
        aA[1] = __ldg(reinterpret_cast<const float4*>(arow0 + j0 + 16 + 4 * tid4));
        aB[0] = __ldg(reinterpret_cast<const float4*>(arow1 + j0 + 4 * tid4));
        aB[1] = __ldg(reinterpret_cast<const float4*>(arow1 + j0 + 16 + 4 * tid4));

        __syncthreads();

        if (n < 15) {
            stageG(sm, buf ^ 1, b, jc + 1, h, t);
            if (t < 32)
                sm.Rv_s[buf ^ 1][t] =
                    __ldg(&Rv_glob[(b * NN + j0 + 32 + t) * NH + h]);
        }

#pragma unroll
        for (int kg = 0; kg < 2; kg++) {
            float4 rv0 = sm.Rv_s[buf][kg * 16 + 4 * tid4 + 0];
            float4 rv1 = sm.Rv_s[buf][kg * 16 + 4 * tid4 + 1];
            float4 rv2 = sm.Rv_s[buf][kg * 16 + 4 * tid4 + 2];
            float4 rv3 = sm.Rv_s[buf][kg * 16 + 4 * tid4 + 3];
            const float* avA = &aA[kg].x;
            const float* avB = &aB[kg].x;
            float w0 = avA[0] * selw(Lp0, Ln0, rv0);
            float w1 = avA[1] * selw(Lp0, Ln0, rv1);
            float w2 = avA[2] * selw(Lp0, Ln0, rv2);
            float w3 = avA[3] * selw(Lp0, Ln0, rv3);
            float v0 = avB[0] * selw(Lp1, Ln1, rv0);
            float v1 = avB[1] * selw(Lp1, Ln1, rv1);
            float v2 = avB[2] * selw(Lp1, Ln1, rv2);
            float v3 = avB[3] * selw(Lp1, Ln1, rv3);

            __nv_bfloat162 hw01 = __floats2bfloat162_rn(w0, w1);
            __nv_bfloat162 hw23 = __floats2bfloat162_rn(w2, w3);
            __nv_bfloat162 hv01 = __floats2bfloat162_rn(v0, v1);
            __nv_bfloat162 hv23 = __floats2bfloat162_rn(v2, v3);
            __nv_bfloat162 lw01 = __floats2bfloat162_rn(
                w0 - __low2float(hw01), w1 - __high2float(hw01));
            __nv_bfloat162 lw23 = __floats2bfloat162_rn(
                w2 - __low2float(hw23), w3 - __high2float(hw23));
            __nv_bfloat162 lv01 = __floats2bfloat162_rn(
                v0 - __low2float(hv01), v1 - __high2float(hv01));
            __nv_bfloat162 lv23 = __floats2bfloat162_rn(
                v2 - __low2float(hv23), v3 - __high2float(hv23));

            uint32_t ah[4] = {bf2u(hw01), bf2u(hv01), bf2u(hw23), bf2u(hv23)};
            uint32_t al[4] = {bf2u(lw01), bf2u(lv01), bf2u(lw23), bf2u(lv23)};

#pragma unroll
            for (int nt = 0; nt < 4; nt++) {
                int row = nt * 8 + gq;
                int wofs = 8 * kg + 2 * tid4;
                uint2 bh2 = *reinterpret_cast<const uint2*>(&sm.Gh[buf][row][wofs]);
                uint2 bl2 = *reinterpret_cast<const uint2*>(&sm.Gl[buf][row][wofs]);
                uint32_t bh[2] = {bh2.x, bh2.y};
                uint32_t bl[2] = {bl2.x, bl2.y};
                mma_bf16(acc[nt], ah, bh);
                mma_bf16(acc[nt], ah, bl);
                mma_bf16(acc[nt], al, bh);
            }
        }
    }

    // epilogue
#pragma unroll
    for (int nt = 0; nt < 4; nt++) {
        float* op0 = dst + (size_t)r0g * OUTF + h * 32 + nt * 8 + 2 * tid4;
        float* op1 = op0 + 8 * OUTF;
        *reinterpret_cast<float2*>(op0) = make_float2(acc[nt][0], acc[nt][1]);
        *reinterpret_cast<float2*>(op1) = make_float2(acc[nt][2], acc[nt][3]);
    }
}

// ---------------------------------------------------------------------------
// K4: out += p1   (combine j-halves)
// ---------------------------------------------------------------------------
__global__ __launch_bounds__(256) void k_comb(float* __restrict__ out) {
    int idx = blockIdx.x * 256 + threadIdx.x;    // < BN*OUTF/4
    float4* o4 = reinterpret_cast<float4*>(out);
    const float4* p4 = reinterpret_cast<const float4*>(p1_buf);
    float4 a = o4[idx], b = p4[idx];
    o4[idx] = make_float4(a.x + b.x, a.y + b.y, a.z + b.z, a.w + b.w);
}

// ---------------------------------------------------------------------------
extern "C" void kernel_launch(void* const* d_in, const int* in_sizes, int n_in,
                              void* d_out, int out_size) {
    const float* h_in = (const float*)d_in[0];
    const float* adj  = (const float*)d_in[1];
    const float* W    = (const float*)d_in[2];
    const float* aw   = (const float*)d_in[3];
    float* out = (float*)d_out;

    k_gemm<<<256, 256>>>(h_in, W, aw);
    k_gpack<<<128, 256>>>();
    k_c<<<4 * (BB * NN) / 32, 512>>>(adj);
    k_rv<<<BN * NH / 256, 256>>>();
    k_aggmma<<<512, 256>>>(adj, out);
    k_comb<<<BN * OUTF / 4 / 256, 256>>>(out);
}

// round 17
// speedup vs baseline: 2.2370x; 1.1743x over previous
#include <cuda_runtime.h>
#include <cuda_bf16.h>
#include <cstdint>

#define BB 4
#define NN 1024
#define INF 256
#define OUTF 256
#define NH 8
#define BN (BB*NN)

// ---------------- scratch (allocation-free) ----------------
__device__ float g_buf[BN*OUTF];    // g = h @ W  (4 MB)
__device__ float p1_buf[BN*OUTF];   // j-half-1 partial (4 MB)
__device__ float Lbuf[BN*16];       // [exp(el) x8, exp(.2el) x8]
__device__ float Rbuf[BN*16];       // [exp(er) x8, exp(.2er) x8]
__device__ float2 Rv_glob[BN*NH];   // (Rp*c, Rn*c) per (b,j,h)
__device__ float4 psum4[BN*NH];     // k_c partial sums, [idx].{x,y,z,w} = iq 0..3
__device__ __align__(16) uint32_t Gpk_hi[BN*OUTF/2];  // packed bf16 pairs (2 MB)
__device__ __align__(16) uint32_t Gpk_lo[BN*OUTF/2];  // lo corrections   (2 MB)

typedef unsigned long long u64;
union U2 { u64 u; float2 f; };

__device__ __forceinline__ u64 pack2s(float v) {
    u64 r; asm("mov.b64 %0, {%1, %1};" : "=l"(r) : "f"(v)); return r;
}
__device__ __forceinline__ u64 mul2(u64 a, u64 b) {
    u64 r; asm("mul.rn.f32x2 %0, %1, %2;" : "=l"(r) : "l"(a), "l"(b)); return r;
}
__device__ __forceinline__ void ffma2(u64& d, u64 a, u64 b) {
    asm("fma.rn.f32x2 %0, %1, %2, %0;" : "+l"(d) : "l"(a), "l"(b));
}

__device__ __forceinline__ uint32_t bf2u(__nv_bfloat162 v) {
    return *reinterpret_cast<uint32_t*>(&v);
}
__device__ __forceinline__ void mma_bf16(float* d, const uint32_t* a,
                                         const uint32_t* b) {
    asm volatile(
        "mma.sync.aligned.m16n8k16.row.col.f32.bf16.bf16.f32 "
        "{%0,%1,%2,%3}, {%4,%5,%6,%7}, {%8,%9}, {%0,%1,%2,%3};"
        : "+f"(d[0]), "+f"(d[1]), "+f"(d[2]), "+f"(d[3])
        : "r"(a[0]), "r"(a[1]), "r"(a[2]), "r"(a[3]), "r"(b[0]), "r"(b[1]));
}

// split a float pair into bf16x2 hi + lo words
__device__ __forceinline__ void split2(float a0, float a1,
                                       uint32_t& hi, uint32_t& lo) {
    __nv_bfloat162 h = __floats2bfloat162_rn(a0, a1);
    __nv_bfloat162 l = __floats2bfloat162_rn(a0 - __low2float(h),
                                             a1 - __high2float(h));
    hi = bf2u(h); lo = bf2u(l);
}

// ---------------------------------------------------------------------------
// K1 (tensor): g = X @ W via bf16 m16n8k16 3-term, fused el/er+exp epilogue.
// (identical to R15/R16)
// ---------------------------------------------------------------------------
__global__ __launch_bounds__(256) void k_gemm(const float* __restrict__ X,
                                              const float* __restrict__ W,
                                              const float* __restrict__ aw) {
    __shared__ uint32_t Bh[8][68];
    __shared__ uint32_t Bl[8][68];
    const int t = threadIdx.x;
    const int rb = blockIdx.x >> 2, cb = blockIdx.x & 3;
    const int lane = t & 31, w = t >> 5;
    const int gq = lane >> 2, t4 = lane & 3;
    const int wr = w & 3;
    const int wh = w >> 2;
    const int grow0 = rb * 64 + wr * 16 + gq;

    const int kk = t >> 4;
    const int nb = (t & 15) * 4;
    const bool evenk = (kk & 1) == 0;
    const int pidx = kk >> 1;

    float acc[4][4];
#pragma unroll
    for (int nt = 0; nt < 4; nt++)
#pragma unroll
        for (int c = 0; c < 4; c++) acc[nt][c] = 0.f;

    const float* xrow0 = X + (size_t)grow0 * INF;
    const float* xrow1 = xrow0 + 8 * INF;

    float4 wv = __ldg(reinterpret_cast<const float4*>(
        &W[kk * OUTF + cb * 64 + nb]));
    float4 xa = __ldg(reinterpret_cast<const float4*>(xrow0 + 4 * t4));
    float4 xb = __ldg(reinterpret_cast<const float4*>(xrow1 + 4 * t4));

    for (int k0 = 0; k0 < INF; k0 += 16) {
        __syncthreads();
        {
            float pw[4] = {wv.x, wv.y, wv.z, wv.w};
            float qw[4];
#pragma unroll
            for (int e = 0; e < 4; e++)
                qw[e] = __shfl_xor_sync(0xffffffffu, pw[e], 16);
#pragma unroll
            for (int e = 0; e < 4; e++) {
                float a0 = evenk ? pw[e] : qw[e];
                float a1 = evenk ? qw[e] : pw[e];
                __nv_bfloat162 h = __floats2bfloat162_rn(a0, a1);
                if (evenk) {
                    Bh[pidx][nb + e] = bf2u(h);
                } else {
                    __nv_bfloat162 l = __floats2bfloat162_rn(
                        a0 - __low2float(h), a1 - __high2float(h));
                    Bl[pidx][nb + e] = bf2u(l);
                }
            }
        }
        __syncthreads();

        if (k0 + 16 < INF)
            wv = __ldg(reinterpret_cast<const float4*>(
                &W[(k0 + 16 + kk) * OUTF + cb * 64 + nb]));

        uint32_t ah[4], al[4];
        split2(xa.x, xa.y, ah[0], al[0]);
        split2(xb.x, xb.y, ah[1], al[1]);
        split2(xa.z, xa.w, ah[2], al[2]);
        split2(xb.z, xb.w, ah[3], al[3]);

        if (k0 + 16 < INF) {
            xa = __ldg(reinterpret_cast<const float4*>(xrow0 + k0 + 16 + 4 * t4));
            xb = __ldg(reinterpret_cast<const float4*>(xrow1 + k0 + 16 + 4 * t4));
        }

#pragma unroll
        for (int nt = 0; nt < 4; nt++) {
            int n = wh * 32 + nt * 8 + gq;
            uint32_t bh[2] = {Bh[2 * t4][n], Bh[2 * t4 + 1][n]};
            uint32_t bl[2] = {Bl[2 * t4][n], Bl[2 * t4 + 1][n]};
            mma_bf16(acc[nt], ah, bh);
            mma_bf16(acc[nt], ah, bl);
            mma_bf16(acc[nt], al, bh);
        }
    }

    const int head = cb * 2 + wh;
    float e_l[2] = {0.f, 0.f}, e_r[2] = {0.f, 0.f};
#pragma unroll
    for (int nt = 0; nt < 4; nt++) {
        int d0 = nt * 8 + 2 * t4;
        float wl0 = __ldg(&aw[d0]),      wl1 = __ldg(&aw[d0 + 1]);
        float wr0 = __ldg(&aw[32 + d0]), wr1 = __ldg(&aw[32 + d0 + 1]);
        e_l[0] += acc[nt][0] * wl0 + acc[nt][1] * wl1;
        e_l[1] += acc[nt][2] * wl0 + acc[nt][3] * wl1;
        e_r[0] += acc[nt][0] * wr0 + acc[nt][1] * wr1;
        e_r[1] += acc[nt][2] * wr0 + acc[nt][3] * wr1;

        float* gp0 = g_buf + (size_t)grow0 * OUTF + cb * 64 + wh * 32 + d0;
        *reinterpret_cast<float2*>(gp0) = make_float2(acc[nt][0], acc[nt][1]);
        *reinterpret_cast<float2*>(gp0 + 8 * OUTF) =
            make_float2(acc[nt][2], acc[nt][3]);
    }
#pragma unroll
    for (int rh = 0; rh < 2; rh++) {
        e_l[rh] += __shfl_xor_sync(0xffffffffu, e_l[rh], 1);
        e_l[rh] += __shfl_xor_sync(0xffffffffu, e_l[rh], 2);
        e_r[rh] += __shfl_xor_sync(0xffffffffu, e_r[rh], 1);
        e_r[rh] += __shfl_xor_sync(0xffffffffu, e_r[rh], 2);
    }
    if (t4 == 0) {
#pragma unroll
        for (int rh = 0; rh < 2; rh++) {
            int row = grow0 + rh * 8;
            Lbuf[row * 16 + head]     = __expf(e_l[rh]);
            Lbuf[row * 16 + 8 + head] = __expf(0.2f * e_l[rh]);
            Rbuf[row * 16 + head]     = __expf(e_r[rh]);
            Rbuf[row * 16 + 8 + head] = __expf(0.2f * e_r[rh]);
        }
    }
}

// ---------------------------------------------------------------------------
// K_gpack: g -> packed bf16 hi/lo pair-words (identical to R16).
// ---------------------------------------------------------------------------
__global__ __launch_bounds__(256) void k_gpack() {
    __shared__ float gs[32][264];
    const int t = threadIdx.x;
    const int b = blockIdx.x >> 5, jc = blockIdx.x & 31;

    const float4* src = reinterpret_cast<const float4*>(
        g_buf + (size_t)(b * NN + jc * 32) * OUTF);
#pragma unroll
    for (int m = 0; m < 8; m++) {
        int v = t + m * 256;
        int row = v >> 6, c4 = v & 63;
        float4 x = src[(size_t)row * 64 + c4];
        *reinterpret_cast<float4*>(&gs[row][c4 * 4]) = x;
    }
    __syncthreads();

    const int h = t >> 5, d = t & 31;
    uint32_t wh[16], wl[16];
#pragma unroll
    for (int p = 0; p < 16; p++) {
        float a  = gs[2 * p][h * 32 + d];
        float bf = gs[2 * p + 1][h * 32 + d];
        __nv_bfloat16 ha = __float2bfloat16(a);
        __nv_bfloat16 hb = __float2bfloat16(bf);
        __nv_bfloat16 la = __float2bfloat16(a - __bfloat162float(ha));
        __nv_bfloat16 lb = __float2bfloat16(bf - __bfloat162float(hb));
        wh[p] = (uint32_t)__bfloat16_as_ushort(ha) |
                ((uint32_t)__bfloat16_as_ushort(hb) << 16);
        wl[p] = (uint32_t)__bfloat16_as_ushort(la) |
                ((uint32_t)__bfloat16_as_ushort(lb) << 16);
    }
    size_t base = ((size_t)((b * 8 + h) * 32 + jc) << 9) + d * 16;
#pragma unroll
    for (int q = 0; q < 4; q++) {
        *reinterpret_cast<uint4*>(&Gpk_hi[base + 4 * q]) =
            make_uint4(wh[4*q], wh[4*q+1], wh[4*q+2], wh[4*q+3]);
        *reinterpret_cast<uint4*>(&Gpk_lo[base + 4 * q]) =
            make_uint4(wl[4*q], wl[4*q+1], wl[4*q+2], wl[4*q+3]);
    }
}

// ---------------------------------------------------------------------------
// K2: partial column sums (i-quarter). Packed f32x2 + max formulation:
// w = max(EPl*EPr, ENl*ENr). Grid 512 = (iq, b, j-chunk).
// ---------------------------------------------------------------------------
__global__ __launch_bounds__(512) void k_c(const float* __restrict__ adj) {
    __shared__ float ssum[16][32][8];
    const int t = threadIdx.x;
    const int iq = blockIdx.x >> 7;
    const int b = (blockIdx.x >> 5) & 3;
    const int j0 = (blockIdx.x & 31) * 32;
    const int jl = t & 31, ig = t >> 5;

    const ulonglong2* rr = reinterpret_cast<const ulonglong2*>(
        &Rbuf[(b * NN + j0 + jl) * 16]);
    ulonglong2 r0 = rr[0], r1 = rr[1], r2 = rr[2], r3 = rr[3];
    u64 EPr2[4] = {r0.x, r0.y, r1.x, r1.y};
    u64 ENr2[4] = {r2.x, r2.y, r3.x, r3.y};

    u64 acc2[4] = {0ull, 0ull, 0ull, 0ull};

    const int ibeg = iq * 256;
    const float* adjcol = adj + (size_t)b * NN * NN + j0 + jl;
#pragma unroll 4
    for (int i = ibeg + ig; i < ibeg + 256; i += 16) {
        float a = __ldg(adjcol + (size_t)i * NN);
        u64 a2 = pack2s(a);
        const ulonglong2* lr = reinterpret_cast<const ulonglong2*>(
            &Lbuf[(b * NN + i) * 16]);
        ulonglong2 l0 = __ldg(&lr[0]), l1 = __ldg(&lr[1]);
        ulonglong2 l2 = __ldg(&lr[2]), l3 = __ldg(&lr[3]);
        u64 EPl2[4] = {l0.x, l0.y, l1.x, l1.y};
        u64 ENl2[4] = {l2.x, l2.y, l3.x, l3.y};
#pragma unroll
        for (int p = 0; p < 4; p++) {
            U2 pp, qq, ww;
            pp.u = mul2(EPl2[p], EPr2[p]);
            qq.u = mul2(ENl2[p], ENr2[p]);
            ww.f.x = fmaxf(pp.f.x, qq.f.x);
            ww.f.y = fmaxf(pp.f.y, qq.f.y);
            ffma2(acc2[p], a2, ww.u);
        }
    }
#pragma unroll
    for (int p = 0; p < 4; p++) {
        U2 v; v.u = acc2[p];
        ssum[ig][jl][2 * p]     = v.f.x;
        ssum[ig][jl][2 * p + 1] = v.f.y;
    }
    __syncthreads();

    if (t < 256) {
        int jl2 = t >> 3, h = t & 7;
        float s = 0.f;
#pragma unroll
        for (int g = 0; g < 16; g++) s += ssum[g][jl2][h];
        reinterpret_cast<float*>(&psum4[(b * NN + j0 + jl2) * NH + h])[iq] = s;
    }
}

// ---------------------------------------------------------------------------
// K_rv: one float4 read per idx -> Rv_glob = (Rp*c, Rn*c).
// ---------------------------------------------------------------------------
__global__ __launch_bounds__(256) void k_rv() {
    int idx = blockIdx.x * 256 + threadIdx.x;     // < BN*NH
    float4 ps = psum4[idx];
    float cc = 1.0f / (ps.x + ps.y + ps.z + ps.w);
    int row = idx >> 3, h = idx & 7;
    Rv_glob[idx] = make_float2(Rbuf[row * 16 + h] * cc,
                               Rbuf[row * 16 + 8 + h] * cc);
}

// ---------------------------------------------------------------------------
// K3 (tensor, bf16 m16n8k16 3-term): R16 + max-selw + float2 Rv.
// ---------------------------------------------------------------------------
#define GSTR 20
struct SmemT {
    uint32_t Gh[2][32][GSTR];   // 5 KB
    uint32_t Gl[2][32][GSTR];   // 5 KB
    float2   Rv_s[2][32];       // 0.5 KB
};

__device__ __forceinline__ void stageG(SmemT& sm, int buf, int b, int jc,
                                       int h, int t) {
    const uint32_t* src = (t < 128 ? Gpk_hi : Gpk_lo) +
                          ((size_t)((b * 8 + h) * 32 + jc) << 9);
    int tt = t & 127;
    uint4 v = __ldg(reinterpret_cast<const uint4*>(src) + tt);
    int d = tt >> 2, w0 = (tt & 3) * 4;
    uint32_t* dstrow = (t < 128 ? sm.Gh[buf][d] : sm.Gl[buf][d]);
    *reinterpret_cast<uint4*>(&dstrow[w0]) = v;
}

__device__ __forceinline__ float selw(float Lp, float Ln, float2 rv) {
    return fmaxf(Lp * rv.x, Ln * rv.y);
}

__global__ __launch_bounds__(256, 3) void k_aggmma(const float* __restrict__ adj,
                                                   float* __restrict__ out) {
    __shared__ SmemT sm;
    const int t = threadIdx.x;
    const int bid = blockIdx.x;
    const int jh = bid >> 8;
    const int b  = (bid >> 6) & 3;
    const int h  = (bid >> 3) & 7;
    const int i0 = (bid & 7) * 128;
    const int jbase = jh * 512;
    float* dst = jh ? p1_buf : out;

    const int lane = t & 31;
    const int gq = lane >> 2, tid4 = lane & 3;
    const int m0 = (t >> 5) * 16;

    const int r0g = b * NN + i0 + m0 + gq;
    const float Lp0 = Lbuf[r0g * 16 + h],       Ln0 = Lbuf[r0g * 16 + 8 + h];
    const float Lp1 = Lbuf[(r0g + 8) * 16 + h], Ln1 = Lbuf[(r0g + 8) * 16 + 8 + h];

    float acc[4][4];
#pragma unroll
    for (int nt = 0; nt < 4; nt++)
#pragma unroll
        for (int c = 0; c < 4; c++) acc[nt][c] = 0.f;

    // prologue
    stageG(sm, 0, b, jh * 16, h, t);
    if (t < 32)
        sm.Rv_s[0][t] = __ldg(&Rv_glob[(b * NN + jbase + t) * NH + h]);

    const float* arow0 = adj + (size_t)r0g * NN;
    const float* arow1 = arow0 + 8 * NN;

#pragma unroll 1
    for (int n = 0; n < 16; n++) {
        const int j0 = jbase + n * 32;
        const int jc = jh * 16 + n;
        const int buf = n & 1;

        float4 aA[2], aB[2];
        aA[0] = __ldg(reinterpret_cast<const float4*>(arow0 + j0 + 4 * tid4));
        aA[1] = __ldg(reinterpret_cast<const float4*>(arow0 + j0 + 16 + 4 * tid4));
        aB[0] = __ldg(reinterpret_cast<const float4*>(arow1 + j0 + 4 * tid4));
        aB[1] = __ldg(reinterpret_cast<const float4*>(arow1 + j0 + 16 + 4 * tid4));

        __syncthreads();

        if (n < 15) {
            stageG(sm, buf ^ 1, b, jc + 1, h, t);
            if (t < 32)
                sm.Rv_s[buf ^ 1][t] =
                    __ldg(&Rv_glob[(b * NN + j0 + 32 + t) * NH + h]);
        }

#pragma unroll
        for (int kg = 0; kg < 2; kg++) {
            float2 rv0 = sm.Rv_s[buf][kg * 16 + 4 * tid4 + 0];
            float2 rv1 = sm.Rv_s[buf][kg * 16 + 4 * tid4 + 1];
            float2 rv2 = sm.Rv_s[buf][kg * 16 + 4 * tid4 + 2];
            float2 rv3 = sm.Rv_s[buf][kg * 16 + 4 * tid4 + 3];
            const float* avA = &aA[kg].x;
            const float* avB = &aB[kg].x;
            float w0 = avA[0] * selw(Lp0, Ln0, rv0);
            float w1 = avA[1] * selw(Lp0, Ln0, rv1);
            float w2 = avA[2] * selw(Lp0, Ln0, rv2);
            float w3 = avA[3] * selw(Lp0, Ln0, rv3);
            float v0 = avB[0] * selw(Lp1, Ln1, rv0);
            float v1 = avB[1] * selw(Lp1, Ln1, rv1);
            float v2 = avB[2] * selw(Lp1, Ln1, rv2);
            float v3 = avB[3] * selw(Lp1, Ln1, rv3);

            __nv_bfloat162 hw01 = __floats2bfloat162_rn(w0, w1);
            __nv_bfloat162 hw23 = __floats2bfloat162_rn(w2, w3);
            __nv_bfloat162 hv01 = __floats2bfloat162_rn(v0, v1);
            __nv_bfloat162 hv23 = __floats2bfloat162_rn(v2, v3);
            __nv_bfloat162 lw01 = __floats2bfloat162_rn(
                w0 - __low2float(hw01), w1 - __high2float(hw01));
            __nv_bfloat162 lw23 = __floats2bfloat162_rn(
                w2 - __low2float(hw23), w3 - __high2float(hw23));
            __nv_bfloat162 lv01 = __floats2bfloat162_rn(
                v0 - __low2float(hv01), v1 - __high2float(hv01));
            __nv_bfloat162 lv23 = __floats2bfloat162_rn(
                v2 - __low2float(hv23), v3 - __high2float(hv23));

            uint32_t ah[4] = {bf2u(hw01), bf2u(hv01), bf2u(hw23), bf2u(hv23)};
            uint32_t al[4] = {bf2u(lw01), bf2u(lv01), bf2u(lw23), bf2u(lv23)};

#pragma unroll
            for (int nt = 0; nt < 4; nt++) {
                int row = nt * 8 + gq;
                int wofs = 8 * kg + 2 * tid4;
                uint2 bh2 = *reinterpret_cast<const uint2*>(&sm.Gh[buf][row][wofs]);
                uint2 bl2 = *reinterpret_cast<const uint2*>(&sm.Gl[buf][row][wofs]);
                uint32_t bh[2] = {bh2.x, bh2.y};
                uint32_t bl[2] = {bl2.x, bl2.y};
                mma_bf16(acc[nt], ah, bh);
                mma_bf16(acc[nt], ah, bl);
                mma_bf16(acc[nt], al, bh);
            }
        }
    }

    // epilogue
#pragma unroll
    for (int nt = 0; nt < 4; nt++) {
        float* op0 = dst + (size_t)r0g * OUTF + h * 32 + nt * 8 + 2 * tid4;
        float* op1 = op0 + 8 * OUTF;
        *reinterpret_cast<float2*>(op0) = make_float2(acc[nt][0], acc[nt][1]);
        *reinterpret_cast<float2*>(op1) = make_float2(acc[nt][2], acc[nt][3]);
    }
}

// ---------------------------------------------------------------------------
// K4: out += p1   (combine j-halves)
// ---------------------------------------------------------------------------
__global__ __launch_bounds__(256) void k_comb(float* __restrict__ out) {
    int idx = blockIdx.x * 256 + threadIdx.x;    // < BN*OUTF/4
    float4* o4 = reinterpret_cast<float4*>(out);
    const float4* p4 = reinterpret_cast<const float4*>(p1_buf);
    float4 a = o4[idx], b = p4[idx];
    o4[idx] = make_float4(a.x + b.x, a.y + b.y, a.z + b.z, a.w + b.w);
}

// ---------------------------------------------------------------------------
extern "C" void kernel_launch(void* const* d_in, const int* in_sizes, int n_in,
                              void* d_out, int out_size) {
    const float* h_in = (const float*)d_in[0];
    const float* adj  = (const float*)d_in[1];
    const float* W    = (const float*)d_in[2];
    const float* aw   = (const float*)d_in[3];
    float* out = (float*)d_out;

    k_gemm<<<256, 256>>>(h_in, W, aw);
    k_gpack<<<128, 256>>>();
    k_c<<<4 * (BB * NN) / 32, 512>>>(adj);
    k_rv<<<BN * NH / 256, 256>>>();
    k_aggmma<<<512, 256>>>(adj, out);
    k_comb<<<BN * OUTF / 4 / 256, 256>>>(out);
}